// round 6
// baseline (speedup 1.0000x reference)
#include <cuda_runtime.h>
#include <cstdint>

#define NE 10000
#define NM 2048
#define D  128

// ======================= device scratch (no allocations allowed) ============
__device__ unsigned char g_lev[(size_t)NE * NM];   // 0 = no edge, 1..5 relation
__device__ float g_u[(size_t)NE * NM];             // inv[i][lev[i][j]] (0 if no edge)
__device__ float g_m1[NM * D];                     // relu(x_m @ root1 + b1)
__device__ float g_Z[(size_t)5 * NM * 256];        // [r][j][c]: c<128: x_m@W1[r+1]; c>=128: m1@W2[r+1]
__device__ float g_ebase[(size_t)NE * D];          // x_e @ root1 + b1
__device__ float g_agg[(size_t)NE * 256];          // aggregation result (both convs)

// ======================= small PTX helpers ============
#define CP_ASYNC16(s, g) asm volatile("cp.async.cg.shared.global [%0], [%1], 16;" :: "r"(s), "l"(g))
#define CP_COMMIT()      asm volatile("cp.async.commit_group;" ::: "memory")
#define CP_WAIT0()       asm volatile("cp.async.wait_group 0;" ::: "memory")

__device__ __forceinline__ uint32_t smem_u32(const void* p) {
    uint32_t a;
    asm("{ .reg .u64 t; cvta.to.shared.u64 t, %1; cvt.u32.u64 %0, t; }" : "=r"(a) : "l"(p));
    return a;
}

// ======================= kernel 1: levels + u = inv[lev] ====================
__global__ void k_lev(const float* __restrict__ w) {
    int i = blockIdx.x;
    __shared__ int scnt[5];
    __shared__ float sinv[8];
    if (threadIdx.x < 5) scnt[threadIdx.x] = 0;
    __syncthreads();
    int cnt[5] = {0, 0, 0, 0, 0};
    unsigned char lvs[8];
    const float* wr = w + (size_t)i * NM;
    unsigned char* lr = g_lev + (size_t)i * NM;
    #pragma unroll
    for (int s = 0; s < 8; s++) {
        int j = threadIdx.x + s * 256;
        float v = wr[j];
        int lv = (int)ceilf(v * 6.0f) - 1;
        int o = (lv >= 1 && lv <= 5) ? lv : 0;
        lr[j] = (unsigned char)o;
        lvs[s] = (unsigned char)o;
        if (o) cnt[o - 1]++;
    }
    #pragma unroll
    for (int r = 0; r < 5; r++) {
        int v = cnt[r];
        #pragma unroll
        for (int off = 16; off; off >>= 1) v += __shfl_down_sync(0xffffffffu, v, off);
        if ((threadIdx.x & 31) == 0) atomicAdd(&scnt[r], v);
    }
    __syncthreads();
    if (threadIdx.x < 8) {
        float iv = 0.0f;
        if (threadIdx.x >= 1 && threadIdx.x <= 5) {
            int c = scnt[threadIdx.x - 1];
            iv = (c > 0) ? 1.0f / (float)c : 0.0f;
        }
        sinv[threadIdx.x] = iv;
    }
    __syncthreads();
    float* ur = g_u + (size_t)i * NM;
    #pragma unroll
    for (int s = 0; s < 8; s++) {
        int j = threadIdx.x + s * 256;
        ur[j] = sinv[lvs[s]];
    }
}

// ======================= kernel 2: m1 = relu(x_m @ root1 + b1) ===============
__global__ void k_m1(const float* __restrict__ xm, const float* __restrict__ root1,
                     const float* __restrict__ b1) {
    int j0 = blockIdx.x * 8;
    int c = threadIdx.x;
    __shared__ float xs[8][128];
    for (int t = c; t < 8 * 128; t += 128) xs[t >> 7][t & 127] = xm[(size_t)(j0 + (t >> 7)) * D + (t & 127)];
    __syncthreads();
    float a[8] = {0, 0, 0, 0, 0, 0, 0, 0};
    #pragma unroll 4
    for (int k = 0; k < 128; k++) {
        float wv = root1[k * D + c];
        #pragma unroll
        for (int e = 0; e < 8; e++) a[e] += xs[e][k] * wv;
    }
    float bb = b1[c];
    #pragma unroll
    for (int e = 0; e < 8; e++) g_m1[(size_t)(j0 + e) * D + c] = fmaxf(a[e] + bb, 0.0f);
}

// ======================= kernel 3: ebase = x_e @ root1 + b1 ==================
__global__ void k_ebase(const float* __restrict__ xe, const float* __restrict__ root1,
                        const float* __restrict__ b1) {
    int i0 = blockIdx.x * 8;
    int c = threadIdx.x;
    __shared__ float xs[8][128];
    for (int t = c; t < 8 * 128; t += 128) xs[t >> 7][t & 127] = xe[(size_t)(i0 + (t >> 7)) * D + (t & 127)];
    __syncthreads();
    float a[8] = {0, 0, 0, 0, 0, 0, 0, 0};
    #pragma unroll 4
    for (int k = 0; k < 128; k++) {
        float wv = root1[k * D + c];
        #pragma unroll
        for (int e = 0; e < 8; e++) a[e] += xs[e][k] * wv;
    }
    float bb = b1[c];
    #pragma unroll
    for (int e = 0; e < 8; e++) g_ebase[(size_t)(i0 + e) * D + c] = a[e] + bb;
}

// ======================= kernel 4: Z[r][j][c] = cat(x_m@W1[r+1], m1@W2[r+1]) =
__global__ void k_Z(const float* __restrict__ xm, const float* __restrict__ W1,
                    const float* __restrict__ W2) {
    int ri = blockIdx.y;
    int j0 = blockIdx.x * 16;
    __shared__ float xs[16][128], ms[16][128];
    for (int t = threadIdx.x; t < 16 * 128; t += 256) {
        int e = t >> 7, k = t & 127;
        xs[e][k] = xm[(size_t)(j0 + e) * D + k];
        ms[e][k] = g_m1[(size_t)(j0 + e) * D + k];
    }
    __syncthreads();
    int c = threadIdx.x;
    int cc = c & 127;
    const float* W = ((c < 128) ? W1 : W2) + (size_t)(ri + 1) * D * D;
    const float(*S)[128] = (c < 128) ? xs : ms;
    float a[16];
    #pragma unroll
    for (int e = 0; e < 16; e++) a[e] = 0.0f;
    #pragma unroll 4
    for (int k = 0; k < 128; k++) {
        float wv = W[k * D + cc];
        #pragma unroll
        for (int e = 0; e < 16; e++) a[e] += S[e][k] * wv;
    }
    #pragma unroll
    for (int e = 0; e < 16; e++)
        g_Z[((size_t)ri * NM + j0 + e) * 256 + c] = a[e];
}

// ======================= kernel 5: fused aggregation (f32x2 FMA) =============
// grid (79, 4): x = 128-entity tile, y = 64-column quarter of the 256 agg cols.
// 512 threads = 16 warps = 4 entity-groups (eg) x 4 col-groups (cg).
// Warp (eg,cg): lane = entity eg*32+lane, covers 16 cols [cg*16, cg*16+16).
// SMEM z-table per j-tile: [TJ=8][6 rows][68 floats]; row 0 = zeros (lev=0),
// rows 1..5 = Z[r][j][ycols]. Row pitch 68 floats -> lev rows land on
// disjoint banks (4*lev offset), so the <=6-address warp LDS is 1 phase.
constexpr int TJ = 8;
constexpr int RP = 68;                     // row pitch (floats)
constexpr int JP = 6 * RP;                 // 408 floats per jj
constexpr int BUF_F = TJ * JP;             // 3264 floats per buffer
constexpr int BUF_B = BUF_F * 4;           // 13056 bytes
constexpr int SM_AGG_BYTES = 2 * BUF_B;    // 26112

__global__ __launch_bounds__(512, 2) void k_agg() {
    extern __shared__ float zs[];
    uint32_t zbase = smem_u32(zs);
    int tid = threadIdx.x;
    int wid = tid >> 5, lane = tid & 31;
    int eg = wid >> 2, cg = wid & 3;

    int i0 = blockIdx.x * 128;
    int ybase = blockIdx.y * 64;

    // zero rows (lev=0) of both buffers: 2 x 8 jj x 64 cols
    for (int t = tid; t < 2 * TJ * 64; t += 512) {
        int b = t / (TJ * 64), rem = t % (TJ * 64);
        int jj = rem >> 6, c = rem & 63;
        zs[b * BUF_F + jj * JP + c] = 0.0f;
    }

    int e = eg * 32 + lane;
    int mrow = min(i0 + e, NE - 1);
    const unsigned char* levp = g_lev + (size_t)mrow * NM;
    const float* up = g_u + (size_t)mrow * NM;

    auto stage = [&](int buf, int j0) {
        uint32_t sb = zbase + buf * BUF_B;
        #pragma unroll
        for (int h = 0; h < 2; h++) {
            int c = tid + h * 512;
            if (c < 640) {
                int jj = c / 80, q = c % 80;
                int ri = q >> 4, c4 = q & 15;
                uint32_t sa = sb + (uint32_t)(jj * JP + (ri + 1) * RP + c4 * 4) * 4u;
                const float* g = g_Z + ((size_t)ri * NM + j0 + jj) * 256 + ybase + c4 * 4;
                CP_ASYNC16(sa, g);
            }
        }
        CP_COMMIT();
    };

    unsigned long long acc[8];
    #pragma unroll
    for (int k = 0; k < 8; k++) acc[k] = 0ull;

    stage(0, 0);

    constexpr int NT = NM / TJ;   // 256 tiles
    for (int t = 0; t < NT; t++) {
        int buf = t & 1;
        CP_WAIT0();
        __syncthreads();
        if (t + 1 < NT) stage(buf ^ 1, (t + 1) * TJ);

        int j0 = t * TJ;
        uint2 lv = *(const uint2*)(levp + j0);
        float4 ua = *(const float4*)(up + j0);
        float4 ub = *(const float4*)(up + j0 + 4);
        uint32_t tbase = zbase + buf * BUF_B + cg * 64;   // cg*16 floats

        #pragma unroll
        for (int jj = 0; jj < TJ; jj++) {
            uint32_t w32 = (jj < 4) ? lv.x : lv.y;
            uint32_t b = (w32 >> ((jj & 3) * 8)) & 0xFFu;
            float uv = (jj == 0) ? ua.x : (jj == 1) ? ua.y : (jj == 2) ? ua.z : (jj == 3) ? ua.w
                     : (jj == 4) ? ub.x : (jj == 5) ? ub.y : (jj == 6) ? ub.z : ub.w;
            unsigned long long ivp;
            asm("mov.b64 %0, {%1, %1};" : "=l"(ivp) : "f"(uv));
            uint32_t za = tbase + jj * (JP * 4) + b * (RP * 4);
            #pragma unroll
            for (int ch = 0; ch < 4; ch++) {
                unsigned long long z0, z1;
                asm volatile("ld.shared.v2.u64 {%0, %1}, [%2];"
                             : "=l"(z0), "=l"(z1) : "r"(za + ch * 16));
                asm("fma.rn.f32x2 %0, %1, %2, %0;" : "+l"(acc[2 * ch])     : "l"(z0), "l"(ivp));
                asm("fma.rn.f32x2 %0, %1, %2, %0;" : "+l"(acc[2 * ch + 1]) : "l"(z1), "l"(ivp));
            }
        }
        __syncthreads();
    }

    if (i0 + e < NE) {
        float* dst = g_agg + (size_t)(i0 + e) * 256 + ybase + cg * 16;
        #pragma unroll
        for (int ch = 0; ch < 4; ch++) {
            union { unsigned long long u; float2 f; } a, b;
            a.u = acc[2 * ch];
            b.u = acc[2 * ch + 1];
            *(float4*)(dst + ch * 4) = make_float4(a.f.x, a.f.y, b.f.x, b.f.y);
        }
    }
}

// ======================= kernel 6: both conv epilogues =======================
// 64 entities per block, 256 threads: pe = tid>>3 in [0,31], entities 2pe, 2pe+1.
constexpr int SM_EPI_BYTES = 64 * 132 * 4;
__global__ __launch_bounds__(256, 1) void k_epi(const float* __restrict__ root2,
                                                const float* __restrict__ b2,
                                                float* __restrict__ out) {
    extern __shared__ float sE1[];   // [64][132]
    int i0 = blockIdx.x * 64;
    int tid = threadIdx.x;

    // e1 = relu(ebase + agg1)
    for (int idx = tid; idx < 64 * 32; idx += 256) {
        int e = idx >> 5, q = idx & 31;
        int i = i0 + e;
        float4 v;
        if (i < NE) {
            float4 p0 = *(const float4*)(g_agg + (size_t)i * 256 + q * 4);
            float4 eb = *(const float4*)(g_ebase + (size_t)i * D + q * 4);
            v.x = fmaxf(p0.x + eb.x, 0.0f);
            v.y = fmaxf(p0.y + eb.y, 0.0f);
            v.z = fmaxf(p0.z + eb.z, 0.0f);
            v.w = fmaxf(p0.w + eb.w, 0.0f);
        } else {
            v = make_float4(0, 0, 0, 0);
        }
        *(float4*)(sE1 + e * 132 + q * 4) = v;
    }
    __syncthreads();

    // out = e1 @ root2 + agg2 + b2 : 2 entities x 16 cols per thread
    int pe = tid >> 3, cg = tid & 7;
    int eA = pe * 2, eB = pe * 2 + 1;
    int iA = i0 + eA, iB = i0 + eB;
    int c0 = cg * 16;
    float4 oA[4], oB[4];
    #pragma unroll
    for (int q = 0; q < 4; q++) {
        float4 bb = *(const float4*)(b2 + c0 + q * 4);
        float4 gA = make_float4(0, 0, 0, 0), gB = make_float4(0, 0, 0, 0);
        if (iA < NE) gA = *(const float4*)(g_agg + (size_t)iA * 256 + 128 + c0 + q * 4);
        if (iB < NE) gB = *(const float4*)(g_agg + (size_t)iB * 256 + 128 + c0 + q * 4);
        oA[q] = make_float4(bb.x + gA.x, bb.y + gA.y, bb.z + gA.z, bb.w + gA.w);
        oB[q] = make_float4(bb.x + gB.x, bb.y + gB.y, bb.z + gB.z, bb.w + gB.w);
    }
    #pragma unroll 4
    for (int kk = 0; kk < 128; kk++) {
        float evA = sE1[eA * 132 + kk];
        float evB = sE1[eB * 132 + kk];
        const float4* r2 = (const float4*)(root2 + kk * D + c0);
        #pragma unroll
        for (int q = 0; q < 4; q++) {
            float4 r = r2[q];
            oA[q].x += evA * r.x; oA[q].y += evA * r.y; oA[q].z += evA * r.z; oA[q].w += evA * r.w;
            oB[q].x += evB * r.x; oB[q].y += evB * r.y; oB[q].z += evB * r.z; oB[q].w += evB * r.w;
        }
    }
    if (iA < NE) {
        #pragma unroll
        for (int q = 0; q < 4; q++) *(float4*)(out + (size_t)iA * D + c0 + q * 4) = oA[q];
    }
    if (iB < NE) {
        #pragma unroll
        for (int q = 0; q < 4; q++) *(float4*)(out + (size_t)iB * D + c0 + q * 4) = oB[q];
    }
}

// ======================= launch =======================
extern "C" void kernel_launch(void* const* d_in, const int* in_sizes, int n_in,
                              void* d_out, int out_size) {
    const float* xe    = (const float*)d_in[0];
    const float* xm    = (const float*)d_in[1];
    const float* w     = (const float*)d_in[2];
    const float* W1    = (const float*)d_in[3];
    const float* root1 = (const float*)d_in[4];
    const float* b1    = (const float*)d_in[5];
    const float* W2    = (const float*)d_in[6];
    const float* root2 = (const float*)d_in[7];
    const float* b2    = (const float*)d_in[8];
    float* out = (float*)d_out;

    k_lev<<<NE, 256>>>(w);
    k_m1<<<NM / 8, 128>>>(xm, root1, b1);
    k_ebase<<<NE / 8, 128>>>(xe, root1, b1);
    k_Z<<<dim3(NM / 16, 5), 256>>>(xm, W1, W2);

    cudaFuncSetAttribute(k_agg, cudaFuncAttributeMaxDynamicSharedMemorySize, SM_AGG_BYTES);
    k_agg<<<dim3(79, 4), 512, SM_AGG_BYTES>>>();

    cudaFuncSetAttribute(k_epi, cudaFuncAttributeMaxDynamicSharedMemorySize, SM_EPI_BYTES);
    k_epi<<<(NE + 63) / 64, 256, SM_EPI_BYTES>>>(root2, b2, out);
}

// round 7
// speedup vs baseline: 1.3855x; 1.3855x over previous
#include <cuda_runtime.h>
#include <cstdint>

#define NE 10000
#define NM 2048
#define D  128
#define NEP 10112            // 79*128, padded entity count (16B-aligned rows)

// ======================= device scratch (no allocations allowed) ============
__device__ unsigned char g_lev[(size_t)NE * NM];    // row-major levels 0..5
__device__ float g_inv[NE * 8];                     // [i][r]: r=0 -> 0, r=1..5 -> 1/cnt
__device__ unsigned char g_levt[(size_t)NM * NEP];  // transposed levels
__device__ float g_ut[(size_t)NM * NEP];            // transposed u = inv[lev]
__device__ float g_m1[NM * D];                      // relu(x_m @ root1 + b1)
__device__ float g_Z[(size_t)5 * NM * 256];         // [r][j][c]: c<128: x_m@W1[r+1]; c>=128: m1@W2[r+1]
__device__ float g_ebase[(size_t)NE * D];           // x_e @ root1 + b1
__device__ float g_agg[(size_t)NE * 256];           // aggregation result (both convs)

// ======================= small PTX helpers ============
#define CP_ASYNC16(s, g) asm volatile("cp.async.cg.shared.global [%0], [%1], 16;" :: "r"(s), "l"(g))
#define CP_COMMIT()      asm volatile("cp.async.commit_group;" ::: "memory")
#define CP_WAIT1()       asm volatile("cp.async.wait_group 1;" ::: "memory")
#define CP_WAIT0()       asm volatile("cp.async.wait_group 0;" ::: "memory")

__device__ __forceinline__ uint32_t smem_u32(const void* p) {
    uint32_t a;
    asm("{ .reg .u64 t; cvta.to.shared.u64 t, %1; cvt.u32.u64 %0, t; }" : "=r"(a) : "l"(p));
    return a;
}

// ======================= kernel 1: levels + inverse counts ===================
__global__ void k_lev(const float* __restrict__ w) {
    int i = blockIdx.x;
    __shared__ int scnt[5];
    if (threadIdx.x < 5) scnt[threadIdx.x] = 0;
    __syncthreads();
    int cnt[5] = {0, 0, 0, 0, 0};
    const float* wr = w + (size_t)i * NM;
    unsigned char* lr = g_lev + (size_t)i * NM;
    #pragma unroll
    for (int s = 0; s < 8; s++) {
        int j = threadIdx.x + s * 256;
        float v = wr[j];
        int lv = (int)ceilf(v * 6.0f) - 1;
        int o = (lv >= 1 && lv <= 5) ? lv : 0;
        lr[j] = (unsigned char)o;
        if (o) cnt[o - 1]++;
    }
    #pragma unroll
    for (int r = 0; r < 5; r++) {
        int v = cnt[r];
        #pragma unroll
        for (int off = 16; off; off >>= 1) v += __shfl_down_sync(0xffffffffu, v, off);
        if ((threadIdx.x & 31) == 0) atomicAdd(&scnt[r], v);
    }
    __syncthreads();
    if (threadIdx.x < 6) {
        float iv = 0.0f;
        if (threadIdx.x >= 1) {
            int c = scnt[threadIdx.x - 1];
            iv = (c > 0) ? 1.0f / (float)c : 0.0f;
        }
        g_inv[i * 8 + threadIdx.x] = iv;
    }
}

// ======================= kernel 1b: transpose lev -> levt, build ut ==========
// block (32,8), tile 32x32 over (i, j).
__global__ void k_tr() {
    __shared__ unsigned char slev[32][33];
    __shared__ float sinv[32][6];
    int j0 = blockIdx.x * 32;
    int i0 = blockIdx.y * 32;
    int tx = threadIdx.x, ty = threadIdx.y;
    #pragma unroll
    for (int dy = 0; dy < 4; dy++) {
        int i = i0 + ty + dy * 8;
        unsigned char v = 0;
        if (i < NE) v = g_lev[(size_t)i * NM + j0 + tx];
        slev[ty + dy * 8][tx] = v;
    }
    int t = ty * 32 + tx;
    if (t < 192) {
        int r = t / 6, k = t - r * 6;
        sinv[r][k] = (i0 + r < NE) ? g_inv[(i0 + r) * 8 + k] : 0.0f;
    }
    __syncthreads();
    #pragma unroll
    for (int dy = 0; dy < 4; dy++) {
        int j = j0 + ty + dy * 8;
        unsigned char b = slev[tx][ty + dy * 8];
        g_levt[(size_t)j * NEP + i0 + tx] = b;
        g_ut[(size_t)j * NEP + i0 + tx] = sinv[tx][b];
    }
}

// ======================= kernel 2: m1 = relu(x_m @ root1 + b1) ===============
__global__ void k_m1(const float* __restrict__ xm, const float* __restrict__ root1,
                     const float* __restrict__ b1) {
    int j0 = blockIdx.x * 8;
    int c = threadIdx.x;
    __shared__ float xs[8][128];
    for (int t = c; t < 8 * 128; t += 128) xs[t >> 7][t & 127] = xm[(size_t)(j0 + (t >> 7)) * D + (t & 127)];
    __syncthreads();
    float a[8] = {0, 0, 0, 0, 0, 0, 0, 0};
    #pragma unroll 4
    for (int k = 0; k < 128; k++) {
        float wv = root1[k * D + c];
        #pragma unroll
        for (int e = 0; e < 8; e++) a[e] += xs[e][k] * wv;
    }
    float bb = b1[c];
    #pragma unroll
    for (int e = 0; e < 8; e++) g_m1[(size_t)(j0 + e) * D + c] = fmaxf(a[e] + bb, 0.0f);
}

// ======================= kernel 3: ebase = x_e @ root1 + b1 ==================
__global__ void k_ebase(const float* __restrict__ xe, const float* __restrict__ root1,
                        const float* __restrict__ b1) {
    int i0 = blockIdx.x * 8;
    int c = threadIdx.x;
    __shared__ float xs[8][128];
    for (int t = c; t < 8 * 128; t += 128) xs[t >> 7][t & 127] = xe[(size_t)(i0 + (t >> 7)) * D + (t & 127)];
    __syncthreads();
    float a[8] = {0, 0, 0, 0, 0, 0, 0, 0};
    #pragma unroll 4
    for (int k = 0; k < 128; k++) {
        float wv = root1[k * D + c];
        #pragma unroll
        for (int e = 0; e < 8; e++) a[e] += xs[e][k] * wv;
    }
    float bb = b1[c];
    #pragma unroll
    for (int e = 0; e < 8; e++) g_ebase[(size_t)(i0 + e) * D + c] = a[e] + bb;
}

// ======================= kernel 4: Z[r][j][c] = cat(x_m@W1[r+1], m1@W2[r+1]) =
__global__ void k_Z(const float* __restrict__ xm, const float* __restrict__ W1,
                    const float* __restrict__ W2) {
    int ri = blockIdx.y;
    int j0 = blockIdx.x * 16;
    __shared__ float xs[16][128], ms[16][128];
    for (int t = threadIdx.x; t < 16 * 128; t += 256) {
        int e = t >> 7, k = t & 127;
        xs[e][k] = xm[(size_t)(j0 + e) * D + k];
        ms[e][k] = g_m1[(size_t)(j0 + e) * D + k];
    }
    __syncthreads();
    int c = threadIdx.x;
    int cc = c & 127;
    const float* W = ((c < 128) ? W1 : W2) + (size_t)(ri + 1) * D * D;
    const float(*S)[128] = (c < 128) ? xs : ms;
    float a[16];
    #pragma unroll
    for (int e = 0; e < 16; e++) a[e] = 0.0f;
    #pragma unroll 4
    for (int k = 0; k < 128; k++) {
        float wv = W[k * D + cc];
        #pragma unroll
        for (int e = 0; e < 16; e++) a[e] += S[e][k] * wv;
    }
    #pragma unroll
    for (int e = 0; e < 16; e++)
        g_Z[((size_t)ri * NM + j0 + e) * 256 + c] = a[e];
}

// ======================= kernel 5: fused aggregation (f32x2 FMA) =============
// grid (79, 4): x = 128-entity tile, y = 64-column quarter of the 256 agg cols.
// 512 threads = 16 warps = 4 entity-groups (eg) x 4 col-groups (cg).
// All global traffic via coalesced cp.async, 3-stage ring (z-table + u + lev).
constexpr int TJ = 8;
constexpr int RP = 68;                       // z row pitch (floats)
constexpr int JP = 6 * RP;                   // 408 floats per jj (row 0 = zeros)
constexpr int ZB = TJ * JP * 4;              // 13056 bytes
constexpr int UOFF = ZB;                     // u slab: 8*128*4 = 4096 bytes
constexpr int LOFF = ZB + 4096;              // lev slab: 8*128 = 1024 bytes
constexpr int STAGE_B = LOFF + 1024;         // 18176 bytes per stage
constexpr int SM_AGG_BYTES = 3 * STAGE_B;    // 54528

__global__ __launch_bounds__(512, 2) void k_agg() {
    extern __shared__ float zs[];
    uint32_t zbase = smem_u32(zs);
    int tid = threadIdx.x;
    int wid = tid >> 5, lane = tid & 31;
    int eg = wid >> 2, cg = wid & 3;

    int i0 = blockIdx.x * 128;
    int ybase = blockIdx.y * 64;

    // zero the lev=0 z-rows of all 3 stages
    for (int t = tid; t < 3 * TJ * 64; t += 512) {
        int b = t / (TJ * 64), rem = t % (TJ * 64);
        int jj = rem >> 6, c = rem & 63;
        zs[b * (STAGE_B / 4) + jj * JP + c] = 0.0f;
    }

    auto stage = [&](int buf, int j0) {
        uint32_t sb = zbase + buf * STAGE_B;
        #pragma unroll
        for (int h = 0; h < 2; h++) {
            int c = tid + h * 512;
            if (c < 640) {                       // z-table: 5 relations x 8 jj x 64 cols
                int jj = c / 80, q = c % 80;
                int ri = q >> 4, c4 = q & 15;
                uint32_t sa = sb + (uint32_t)(jj * (JP * 4) + (ri + 1) * (RP * 4) + c4 * 16);
                const float* g = g_Z + ((size_t)ri * NM + j0 + jj) * 256 + ybase + c4 * 4;
                CP_ASYNC16(sa, g);
            } else if (c < 896) {                // u slab: 8 jj x 128 entities
                int q = c - 640;
                int jj = q >> 5, e4 = q & 31;
                uint32_t sa = sb + UOFF + (uint32_t)(jj * 512 + e4 * 16);
                const float* g = g_ut + (size_t)(j0 + jj) * NEP + i0 + e4 * 4;
                CP_ASYNC16(sa, g);
            } else if (c < 960) {                // lev slab: 8 jj x 128 entities (bytes)
                int q = c - 896;
                int jj = q >> 3, e16 = q & 7;
                uint32_t sa = sb + LOFF + (uint32_t)(jj * 128 + e16 * 16);
                const unsigned char* g = g_levt + (size_t)(j0 + jj) * NEP + i0 + e16 * 16;
                CP_ASYNC16(sa, g);
            }
        }
        CP_COMMIT();
    };

    unsigned long long acc[8];
    #pragma unroll
    for (int k = 0; k < 8; k++) acc[k] = 0ull;

    stage(0, 0);
    stage(1, TJ);

    int e = eg * 32 + lane;
    constexpr int NT = NM / TJ;   // 256 tiles
    for (int t = 0; t < NT; t++) {
        int buf = t % 3;
        if (t + 1 < NT) CP_WAIT1(); else CP_WAIT0();
        __syncthreads();
        if (t + 2 < NT) stage((t + 2) % 3, (t + 2) * TJ);

        uint32_t bb = zbase + buf * STAGE_B;
        uint32_t ub = bb + UOFF + e * 4;
        uint32_t lb = bb + LOFF + e;
        uint32_t zb = bb + cg * 64;

        #pragma unroll
        for (int jj = 0; jj < TJ; jj++) {
            float uv;
            uint32_t b;
            asm volatile("ld.shared.f32 %0, [%1];" : "=f"(uv) : "r"(ub + jj * 512));
            asm volatile("ld.shared.u8 %0, [%1];" : "=r"(b) : "r"(lb + jj * 128));
            unsigned long long ivp;
            asm("mov.b64 %0, {%1, %1};" : "=l"(ivp) : "f"(uv));
            uint32_t za = zb + jj * (JP * 4) + b * (RP * 4);
            #pragma unroll
            for (int ch = 0; ch < 4; ch++) {
                unsigned long long z0, z1;
                asm volatile("ld.shared.v2.u64 {%0, %1}, [%2];"
                             : "=l"(z0), "=l"(z1) : "r"(za + ch * 16));
                asm("fma.rn.f32x2 %0, %1, %2, %0;" : "+l"(acc[2 * ch])     : "l"(z0), "l"(ivp));
                asm("fma.rn.f32x2 %0, %1, %2, %0;" : "+l"(acc[2 * ch + 1]) : "l"(z1), "l"(ivp));
            }
        }
        __syncthreads();
    }

    if (i0 + e < NE) {
        float* dst = g_agg + (size_t)(i0 + e) * 256 + ybase + cg * 16;
        #pragma unroll
        for (int ch = 0; ch < 4; ch++) {
            union { unsigned long long u; float2 f; } a, b;
            a.u = acc[2 * ch];
            b.u = acc[2 * ch + 1];
            *(float4*)(dst + ch * 4) = make_float4(a.f.x, a.f.y, b.f.x, b.f.y);
        }
    }
}

// ======================= kernel 6: both conv epilogues =======================
constexpr int SM_EPI_BYTES = 64 * 132 * 4;
__global__ __launch_bounds__(256, 1) void k_epi(const float* __restrict__ root2,
                                                const float* __restrict__ b2,
                                                float* __restrict__ out) {
    extern __shared__ float sE1[];   // [64][132]
    int i0 = blockIdx.x * 64;
    int tid = threadIdx.x;

    for (int idx = tid; idx < 64 * 32; idx += 256) {
        int e = idx >> 5, q = idx & 31;
        int i = i0 + e;
        float4 v;
        if (i < NE) {
            float4 p0 = *(const float4*)(g_agg + (size_t)i * 256 + q * 4);
            float4 eb = *(const float4*)(g_ebase + (size_t)i * D + q * 4);
            v.x = fmaxf(p0.x + eb.x, 0.0f);
            v.y = fmaxf(p0.y + eb.y, 0.0f);
            v.z = fmaxf(p0.z + eb.z, 0.0f);
            v.w = fmaxf(p0.w + eb.w, 0.0f);
        } else {
            v = make_float4(0, 0, 0, 0);
        }
        *(float4*)(sE1 + e * 132 + q * 4) = v;
    }
    __syncthreads();

    int pe = tid >> 3, cg = tid & 7;
    int eA = pe * 2, eB = pe * 2 + 1;
    int iA = i0 + eA, iB = i0 + eB;
    int c0 = cg * 16;
    float4 oA[4], oB[4];
    #pragma unroll
    for (int q = 0; q < 4; q++) {
        float4 bb = *(const float4*)(b2 + c0 + q * 4);
        float4 gA = make_float4(0, 0, 0, 0), gB = make_float4(0, 0, 0, 0);
        if (iA < NE) gA = *(const float4*)(g_agg + (size_t)iA * 256 + 128 + c0 + q * 4);
        if (iB < NE) gB = *(const float4*)(g_agg + (size_t)iB * 256 + 128 + c0 + q * 4);
        oA[q] = make_float4(bb.x + gA.x, bb.y + gA.y, bb.z + gA.z, bb.w + gA.w);
        oB[q] = make_float4(bb.x + gB.x, bb.y + gB.y, bb.z + gB.z, bb.w + gB.w);
    }
    #pragma unroll 4
    for (int kk = 0; kk < 128; kk++) {
        float evA = sE1[eA * 132 + kk];
        float evB = sE1[eB * 132 + kk];
        const float4* r2 = (const float4*)(root2 + kk * D + c0);
        #pragma unroll
        for (int q = 0; q < 4; q++) {
            float4 r = r2[q];
            oA[q].x += evA * r.x; oA[q].y += evA * r.y; oA[q].z += evA * r.z; oA[q].w += evA * r.w;
            oB[q].x += evB * r.x; oB[q].y += evB * r.y; oB[q].z += evB * r.z; oB[q].w += evB * r.w;
        }
    }
    if (iA < NE) {
        #pragma unroll
        for (int q = 0; q < 4; q++) *(float4*)(out + (size_t)iA * D + c0 + q * 4) = oA[q];
    }
    if (iB < NE) {
        #pragma unroll
        for (int q = 0; q < 4; q++) *(float4*)(out + (size_t)iB * D + c0 + q * 4) = oB[q];
    }
}

// ======================= launch =======================
extern "C" void kernel_launch(void* const* d_in, const int* in_sizes, int n_in,
                              void* d_out, int out_size) {
    const float* xe    = (const float*)d_in[0];
    const float* xm    = (const float*)d_in[1];
    const float* w     = (const float*)d_in[2];
    const float* W1    = (const float*)d_in[3];
    const float* root1 = (const float*)d_in[4];
    const float* b1    = (const float*)d_in[5];
    const float* W2    = (const float*)d_in[6];
    const float* root2 = (const float*)d_in[7];
    const float* b2    = (const float*)d_in[8];
    float* out = (float*)d_out;

    k_lev<<<NE, 256>>>(w);
    k_tr<<<dim3(NM / 32, (NEP + 31) / 32), dim3(32, 8)>>>();
    k_m1<<<NM / 8, 128>>>(xm, root1, b1);
    k_ebase<<<NE / 8, 128>>>(xe, root1, b1);
    k_Z<<<dim3(NM / 16, 5), 256>>>(xm, W1, W2);

    cudaFuncSetAttribute(k_agg, cudaFuncAttributeMaxDynamicSharedMemorySize, SM_AGG_BYTES);
    k_agg<<<dim3(79, 4), 512, SM_AGG_BYTES>>>();

    cudaFuncSetAttribute(k_epi, cudaFuncAttributeMaxDynamicSharedMemorySize, SM_EPI_BYTES);
    k_epi<<<(NE + 63) / 64, 256, SM_EPI_BYTES>>>(root2, b2, out);
}

// round 8
// speedup vs baseline: 3.6080x; 2.6041x over previous
#include <cuda_runtime.h>
#include <cuda_fp16.h>
#include <cstdint>

#define NE 10000
#define NM 2048
#define D  128
#define NEP 10112            // 79*128 padded entity count

// ======================= device scratch (no allocations allowed) ============
__device__ unsigned char g_lev[(size_t)NE * NM];   // 0 = no edge, 1..5 relation
__device__ __half g_invh[NE * 8];                  // [i][r] 1/cnt (fp16), r=0 -> 0
__device__ float g_m1[NM * D];                     // relu(x_m @ root1 + b1)
__device__ __half g_ZH[(size_t)5 * 256 * NM];      // [r][n][j] K-major fp16 B
__device__ float g_ebase[(size_t)NE * D];          // x_e @ root1 + b1
__device__ float g_part[(size_t)4 * NEP * 256];    // K-split partials

// ======================= small PTX helpers ============
#define CP_ASYNC16(s, g) asm volatile("cp.async.cg.shared.global [%0], [%1], 16;" :: "r"(s), "l"(g))
#define CP_COMMIT()      asm volatile("cp.async.commit_group;" ::: "memory")
#define CP_WAIT0()       asm volatile("cp.async.wait_group 0;" ::: "memory")

__device__ __forceinline__ uint32_t smem_u32(const void* p) {
    uint32_t a;
    asm("{ .reg .u64 t; cvta.to.shared.u64 t, %1; cvt.u32.u64 %0, t; }" : "=r"(a) : "l"(p));
    return a;
}

__device__ __forceinline__ void mma_f16(float* d, const uint32_t* a, const uint32_t* b) {
    asm volatile(
        "mma.sync.aligned.m16n8k16.row.col.f32.f16.f16.f32 "
        "{%0,%1,%2,%3}, {%4,%5,%6,%7}, {%8,%9}, {%0,%1,%2,%3};"
        : "+f"(d[0]), "+f"(d[1]), "+f"(d[2]), "+f"(d[3])
        : "r"(a[0]), "r"(a[1]), "r"(a[2]), "r"(a[3]), "r"(b[0]), "r"(b[1]));
}

// ======================= kernel 1: levels + inverse counts (fp16) ============
__global__ void k_lev(const float* __restrict__ w) {
    int i = blockIdx.x;
    __shared__ int scnt[5];
    if (threadIdx.x < 5) scnt[threadIdx.x] = 0;
    __syncthreads();
    int cnt[5] = {0, 0, 0, 0, 0};
    const float* wr = w + (size_t)i * NM;
    unsigned char* lr = g_lev + (size_t)i * NM;
    #pragma unroll
    for (int s = 0; s < 8; s++) {
        int j = threadIdx.x + s * 256;
        float v = wr[j];
        int lv = (int)ceilf(v * 6.0f) - 1;
        int o = (lv >= 1 && lv <= 5) ? lv : 0;
        lr[j] = (unsigned char)o;
        if (o) cnt[o - 1]++;
    }
    #pragma unroll
    for (int r = 0; r < 5; r++) {
        int v = cnt[r];
        #pragma unroll
        for (int off = 16; off; off >>= 1) v += __shfl_down_sync(0xffffffffu, v, off);
        if ((threadIdx.x & 31) == 0) atomicAdd(&scnt[r], v);
    }
    __syncthreads();
    if (threadIdx.x < 8) {
        float iv = 0.0f;
        if (threadIdx.x >= 1 && threadIdx.x <= 5) {
            int c = scnt[threadIdx.x - 1];
            iv = (c > 0) ? 1.0f / (float)c : 0.0f;
        }
        g_invh[i * 8 + threadIdx.x] = __float2half(iv);
    }
}

// ======================= kernel 2: m1 = relu(x_m @ root1 + b1) ===============
__global__ void k_m1(const float* __restrict__ xm, const float* __restrict__ root1,
                     const float* __restrict__ b1) {
    int j0 = blockIdx.x * 8;
    int c = threadIdx.x;
    __shared__ float xs[8][128];
    for (int t = c; t < 8 * 128; t += 128) xs[t >> 7][t & 127] = xm[(size_t)(j0 + (t >> 7)) * D + (t & 127)];
    __syncthreads();
    float a[8] = {0, 0, 0, 0, 0, 0, 0, 0};
    #pragma unroll 4
    for (int k = 0; k < 128; k++) {
        float wv = root1[k * D + c];
        #pragma unroll
        for (int e = 0; e < 8; e++) a[e] += xs[e][k] * wv;
    }
    float bb = b1[c];
    #pragma unroll
    for (int e = 0; e < 8; e++) g_m1[(size_t)(j0 + e) * D + c] = fmaxf(a[e] + bb, 0.0f);
}

// ======================= kernel 3: ebase = x_e @ root1 + b1 ==================
__global__ void k_ebase(const float* __restrict__ xe, const float* __restrict__ root1,
                        const float* __restrict__ b1) {
    int i0 = blockIdx.x * 8;
    int c = threadIdx.x;
    __shared__ float xs[8][128];
    for (int t = c; t < 8 * 128; t += 128) xs[t >> 7][t & 127] = xe[(size_t)(i0 + (t >> 7)) * D + (t & 127)];
    __syncthreads();
    float a[8] = {0, 0, 0, 0, 0, 0, 0, 0};
    #pragma unroll 4
    for (int k = 0; k < 128; k++) {
        float wv = root1[k * D + c];
        #pragma unroll
        for (int e = 0; e < 8; e++) a[e] += xs[e][k] * wv;
    }
    float bb = b1[c];
    #pragma unroll
    for (int e = 0; e < 8; e++) g_ebase[(size_t)(i0 + e) * D + c] = a[e] + bb;
}

// ======================= kernel 4: ZH[r][n][j] = fp16 K-major ================
__global__ void k_Z(const float* __restrict__ xm, const float* __restrict__ W1,
                    const float* __restrict__ W2) {
    int ri = blockIdx.y;
    int j0 = blockIdx.x * 16;
    __shared__ float xs[16][128], ms[16][128];
    for (int t = threadIdx.x; t < 16 * 128; t += 256) {
        int e = t >> 7, k = t & 127;
        xs[e][k] = xm[(size_t)(j0 + e) * D + k];
        ms[e][k] = g_m1[(size_t)(j0 + e) * D + k];
    }
    __syncthreads();
    int c = threadIdx.x;
    int cc = c & 127;
    const float* W = ((c < 128) ? W1 : W2) + (size_t)(ri + 1) * D * D;
    const float(*S)[128] = (c < 128) ? xs : ms;
    float a[16];
    #pragma unroll
    for (int e = 0; e < 16; e++) a[e] = 0.0f;
    #pragma unroll 4
    for (int k = 0; k < 128; k++) {
        float wv = W[k * D + cc];
        #pragma unroll
        for (int e = 0; e < 16; e++) a[e] += S[e][k] * wv;
    }
    __half2* dst = (__half2*)(g_ZH + ((size_t)ri * 256 + c) * NM + j0);
    #pragma unroll
    for (int e = 0; e < 8; e++) dst[e] = __floats2half2_rn(a[2 * e], a[2 * e + 1]);
}

// ======================= kernel 5: fp16 mask-GEMM (on-the-fly A) =============
// grid (79, 2, 4): x = M tile (128), y = N half (128 of 256), z = K quarter.
// 512 threads, 16 warps in 4x4 (wm, wn), warp tile 32x32, K-tile 64 fp16.
constexpr int KT = 64;
constexpr int KQ = 2560;
constexpr int ITERS = KQ / KT;             // 40
constexpr int ASTR = 72;                   // fp16 units per smem row (pad)
constexpr int TILE_H = 128 * ASTR;         // 9216 halfs
constexpr int SM_MMA_BYTES = 4 * TILE_H * 2;  // A0,B0,A1,B1 = 73728 B

__global__ __launch_bounds__(512, 2) void k_mma() {
    extern __shared__ __half smh[];
    __half* As[2] = { smh,              smh + 2 * TILE_H };
    __half* Bs[2] = { smh + TILE_H,     smh + 3 * TILE_H };

    int tid = threadIdx.x;
    int wid = tid >> 5, lane = tid & 31;
    int gid = lane >> 2, t4 = lane & 3;
    int wm = wid & 3, wn = wid >> 2;

    int i0 = blockIdx.x * 128;
    int n0g = blockIdx.y * 128;
    int kbase = blockIdx.z * KQ;

    // A-build role: row m = tid>>2, 16-lev chunk q = tid&3
    int am = tid >> 2, aq = tid & 3;
    int mrow = min(i0 + am, NE - 1);
    const unsigned char* levrow = g_lev + (size_t)mrow * NM;
    const __half* invrow = g_invh + mrow * 8;

    auto stageB = [&](int s, int r, int j0) {
        uint32_t sb = smem_u32(Bs[s]);
        #pragma unroll
        for (int h = 0; h < 2; h++) {
            int c = tid + h * 512;
            int n = c >> 3, ch = c & 7;
            uint32_t sa = sb + (uint32_t)(n * (ASTR * 2) + ch * 16);
            const __half* g = g_ZH + ((size_t)(r * 256 + n0g + n)) * NM + j0 + ch * 8;
            CP_ASYNC16(sa, g);
        }
        CP_COMMIT();
    };
    auto buildA = [&](int s, int r, int j0) {
        uint4 u = *(const uint4*)(levrow + j0 + aq * 16);
        unsigned char bts[16];
        *(uint4*)bts = u;
        __half ivh = invrow[r + 1];
        __half z = __ushort_as_half((unsigned short)0);
        uint32_t pk[8];
        unsigned char rv = (unsigned char)(r + 1);
        #pragma unroll
        for (int q = 0; q < 8; q++) {
            __half2 h2;
            h2.x = (bts[2 * q] == rv) ? ivh : z;
            h2.y = (bts[2 * q + 1] == rv) ? ivh : z;
            pk[q] = *(uint32_t*)&h2;
        }
        uint32_t* dst = (uint32_t*)(As[s] + am * ASTR + aq * 16);
        *(uint4*)dst = make_uint4(pk[0], pk[1], pk[2], pk[3]);
        *(uint4*)(dst + 4) = make_uint4(pk[4], pk[5], pk[6], pk[7]);
    };

    float dacc[2][4][4];
    #pragma unroll
    for (int mi = 0; mi < 2; mi++)
        #pragma unroll
        for (int ni = 0; ni < 4; ni++)
            #pragma unroll
            for (int q = 0; q < 4; q++) dacc[mi][ni][q] = 0.0f;

    {
        int kg = kbase;
        stageB(0, kg >> 11, kg & 2047);
        buildA(0, kg >> 11, kg & 2047);
    }

    for (int it = 0; it < ITERS; it++) {
        int s = it & 1;
        CP_WAIT0();
        __syncthreads();
        if (it + 1 < ITERS) {
            int kg = kbase + (it + 1) * KT;
            stageB(s ^ 1, kg >> 11, kg & 2047);
            buildA(s ^ 1, kg >> 11, kg & 2047);
        }

        const __half* A = As[s];
        const __half* B = Bs[s];
        int ra = wm * 32 + gid;
        int nb = wn * 32 + gid;
        #pragma unroll
        for (int kk = 0; kk < 4; kk++) {
            int kc = kk * 16 + t4 * 2;     // fp16 index of first of the pair
            uint32_t af[2][4], bf[4][2];
            #pragma unroll
            for (int mi = 0; mi < 2; mi++) {
                int r = ra + mi * 16;
                af[mi][0] = *(const uint32_t*)(A + r * ASTR + kc);
                af[mi][1] = *(const uint32_t*)(A + (r + 8) * ASTR + kc);
                af[mi][2] = *(const uint32_t*)(A + r * ASTR + kc + 8);
                af[mi][3] = *(const uint32_t*)(A + (r + 8) * ASTR + kc + 8);
            }
            #pragma unroll
            for (int ni = 0; ni < 4; ni++) {
                int n = nb + ni * 8;
                bf[ni][0] = *(const uint32_t*)(B + n * ASTR + kc);
                bf[ni][1] = *(const uint32_t*)(B + n * ASTR + kc + 8);
            }
            #pragma unroll
            for (int mi = 0; mi < 2; mi++)
                #pragma unroll
                for (int ni = 0; ni < 4; ni++)
                    mma_f16(dacc[mi][ni], af[mi], bf[ni]);
        }
        __syncthreads();
    }

    float* dst = g_part + (size_t)blockIdx.z * NEP * 256;
    #pragma unroll
    for (int mi = 0; mi < 2; mi++) {
        int r0 = i0 + wm * 32 + mi * 16 + gid;
        #pragma unroll
        for (int ni = 0; ni < 4; ni++) {
            int cn = n0g + wn * 32 + ni * 8 + 2 * t4;
            *(float2*)(dst + (size_t)r0 * 256 + cn) = make_float2(dacc[mi][ni][0], dacc[mi][ni][1]);
            *(float2*)(dst + (size_t)(r0 + 8) * 256 + cn) = make_float2(dacc[mi][ni][2], dacc[mi][ni][3]);
        }
    }
}

// ======================= kernel 6: reduce 4 partials + both conv epilogues ===
constexpr int SM_EPI_BYTES = 64 * 132 * 4;
__global__ __launch_bounds__(256, 1) void k_epi(const float* __restrict__ root2,
                                                const float* __restrict__ b2,
                                                float* __restrict__ out) {
    extern __shared__ float sE1[];   // [64][132]
    int i0 = blockIdx.x * 64;
    int tid = threadIdx.x;

    // e1 = relu(ebase + agg1)
    for (int idx = tid; idx < 64 * 32; idx += 256) {
        int e = idx >> 5, q = idx & 31;
        int i = i0 + e;
        float4 v = make_float4(0, 0, 0, 0);
        if (i < NE) {
            float4 s = *(const float4*)(g_ebase + (size_t)i * D + q * 4);
            #pragma unroll
            for (int z = 0; z < 4; z++) {
                float4 p = *(const float4*)(g_part + ((size_t)z * NEP + i) * 256 + q * 4);
                s.x += p.x; s.y += p.y; s.z += p.z; s.w += p.w;
            }
            v.x = fmaxf(s.x, 0.0f); v.y = fmaxf(s.y, 0.0f);
            v.z = fmaxf(s.z, 0.0f); v.w = fmaxf(s.w, 0.0f);
        }
        *(float4*)(sE1 + e * 132 + q * 4) = v;
    }
    __syncthreads();

    int pe = tid >> 3, cg = tid & 7;
    int eA = pe * 2, eB = pe * 2 + 1;
    int iA = i0 + eA, iB = i0 + eB;
    int c0 = cg * 16;
    float4 oA[4], oB[4];
    #pragma unroll
    for (int q = 0; q < 4; q++) {
        float4 bb = *(const float4*)(b2 + c0 + q * 4);
        float4 gA = make_float4(0, 0, 0, 0), gB = make_float4(0, 0, 0, 0);
        #pragma unroll
        for (int z = 0; z < 4; z++) {
            if (iA < NE) {
                float4 p = *(const float4*)(g_part + ((size_t)z * NEP + iA) * 256 + 128 + c0 + q * 4);
                gA.x += p.x; gA.y += p.y; gA.z += p.z; gA.w += p.w;
            }
            if (iB < NE) {
                float4 p = *(const float4*)(g_part + ((size_t)z * NEP + iB) * 256 + 128 + c0 + q * 4);
                gB.x += p.x; gB.y += p.y; gB.z += p.z; gB.w += p.w;
            }
        }
        oA[q] = make_float4(bb.x + gA.x, bb.y + gA.y, bb.z + gA.z, bb.w + gA.w);
        oB[q] = make_float4(bb.x + gB.x, bb.y + gB.y, bb.z + gB.z, bb.w + gB.w);
    }
    #pragma unroll 4
    for (int kk = 0; kk < 128; kk++) {
        float evA = sE1[eA * 132 + kk];
        float evB = sE1[eB * 132 + kk];
        const float4* r2 = (const float4*)(root2 + kk * D + c0);
        #pragma unroll
        for (int q = 0; q < 4; q++) {
            float4 r = r2[q];
            oA[q].x += evA * r.x; oA[q].y += evA * r.y; oA[q].z += evA * r.z; oA[q].w += evA * r.w;
            oB[q].x += evB * r.x; oB[q].y += evB * r.y; oB[q].z += evB * r.z; oB[q].w += evB * r.w;
        }
    }
    if (iA < NE) {
        #pragma unroll
        for (int q = 0; q < 4; q++) *(float4*)(out + (size_t)iA * D + c0 + q * 4) = oA[q];
    }
    if (iB < NE) {
        #pragma unroll
        for (int q = 0; q < 4; q++) *(float4*)(out + (size_t)iB * D + c0 + q * 4) = oB[q];
    }
}

// ======================= launch =======================
extern "C" void kernel_launch(void* const* d_in, const int* in_sizes, int n_in,
                              void* d_out, int out_size) {
    const float* xe    = (const float*)d_in[0];
    const float* xm    = (const float*)d_in[1];
    const float* w     = (const float*)d_in[2];
    const float* W1    = (const float*)d_in[3];
    const float* root1 = (const float*)d_in[4];
    const float* b1    = (const float*)d_in[5];
    const float* W2    = (const float*)d_in[6];
    const float* root2 = (const float*)d_in[7];
    const float* b2    = (const float*)d_in[8];
    float* out = (float*)d_out;

    k_lev<<<NE, 256>>>(w);
    k_m1<<<NM / 8, 128>>>(xm, root1, b1);
    k_ebase<<<NE / 8, 128>>>(xe, root1, b1);
    k_Z<<<dim3(NM / 16, 5), 256>>>(xm, W1, W2);

    cudaFuncSetAttribute(k_mma, cudaFuncAttributeMaxDynamicSharedMemorySize, SM_MMA_BYTES);
    k_mma<<<dim3(79, 2, 4), 512, SM_MMA_BYTES>>>();

    cudaFuncSetAttribute(k_epi, cudaFuncAttributeMaxDynamicSharedMemorySize, SM_EPI_BYTES);
    k_epi<<<(NE + 63) / 64, 256, SM_EPI_BYTES>>>(root2, b2, out);
}

// round 9
// speedup vs baseline: 3.7160x; 1.0300x over previous
#include <cuda_runtime.h>
#include <cuda_fp16.h>
#include <cstdint>

#define NE 10000
#define NM 2048
#define D  128
#define NEP 10112            // 79*128 padded entity count

// ======================= device scratch (no allocations allowed) ============
__device__ unsigned char g_lev[(size_t)NE * NM];   // 0 = no edge, 1..5 relation
__device__ __half g_invh[NE * 8];                  // [i][r] 1/cnt (fp16), r=0 -> 0
__device__ float g_m1[NM * D];                     // relu(x_m @ root1 + b1)
__device__ __half g_ZH[(size_t)5 * 256 * NM];      // [r][n][j] K-major fp16 B
__device__ float g_ebase[(size_t)NE * D];          // x_e @ root1 + b1
__device__ float g_part[(size_t)4 * NEP * 256];    // K-split partials

// ======================= small PTX helpers ============
#define CP_ASYNC16(s, g) asm volatile("cp.async.cg.shared.global [%0], [%1], 16;" :: "r"(s), "l"(g))
#define CP_COMMIT()      asm volatile("cp.async.commit_group;" ::: "memory")
#define CP_WAIT0()       asm volatile("cp.async.wait_group 0;" ::: "memory")
#define LDSM_X4(r0, r1, r2, r3, a)                                                   \
    asm volatile("ldmatrix.sync.aligned.m8n8.x4.shared.b16 {%0,%1,%2,%3}, [%4];"     \
                 : "=r"(r0), "=r"(r1), "=r"(r2), "=r"(r3) : "r"(a))

__device__ __forceinline__ uint32_t smem_u32(const void* p) {
    uint32_t a;
    asm("{ .reg .u64 t; cvta.to.shared.u64 t, %1; cvt.u32.u64 %0, t; }" : "=r"(a) : "l"(p));
    return a;
}

__device__ __forceinline__ void mma_f16(float* d, const uint32_t* a, const uint32_t* b) {
    asm volatile(
        "mma.sync.aligned.m16n8k16.row.col.f32.f16.f16.f32 "
        "{%0,%1,%2,%3}, {%4,%5,%6,%7}, {%8,%9}, {%0,%1,%2,%3};"
        : "+f"(d[0]), "+f"(d[1]), "+f"(d[2]), "+f"(d[3])
        : "r"(a[0]), "r"(a[1]), "r"(a[2]), "r"(a[3]), "r"(b[0]), "r"(b[1]));
}

// ======================= kernel 1: levels + inverse counts (fp16) ============
__global__ void k_lev(const float* __restrict__ w) {
    int i = blockIdx.x;
    __shared__ int scnt[5];
    if (threadIdx.x < 5) scnt[threadIdx.x] = 0;
    __syncthreads();
    int cnt[5] = {0, 0, 0, 0, 0};
    const float* wr = w + (size_t)i * NM;
    unsigned char* lr = g_lev + (size_t)i * NM;
    #pragma unroll
    for (int s = 0; s < 8; s++) {
        int j = threadIdx.x + s * 256;
        float v = wr[j];
        int lv = (int)ceilf(v * 6.0f) - 1;
        int o = (lv >= 1 && lv <= 5) ? lv : 0;
        lr[j] = (unsigned char)o;
        if (o) cnt[o - 1]++;
    }
    #pragma unroll
    for (int r = 0; r < 5; r++) {
        int v = cnt[r];
        #pragma unroll
        for (int off = 16; off; off >>= 1) v += __shfl_down_sync(0xffffffffu, v, off);
        if ((threadIdx.x & 31) == 0) atomicAdd(&scnt[r], v);
    }
    __syncthreads();
    if (threadIdx.x < 8) {
        float iv = 0.0f;
        if (threadIdx.x >= 1 && threadIdx.x <= 5) {
            int c = scnt[threadIdx.x - 1];
            iv = (c > 0) ? 1.0f / (float)c : 0.0f;
        }
        g_invh[i * 8 + threadIdx.x] = __float2half(iv);
    }
}

// ======================= kernel 2: m1 = relu(x_m @ root1 + b1), 16 rows ======
__global__ void k_m1(const float* __restrict__ xm, const float* __restrict__ root1,
                     const float* __restrict__ b1) {
    int j0 = blockIdx.x * 16;
    int c = threadIdx.x;
    __shared__ float xs[16][128];
    for (int t = c; t < 16 * 128; t += 128) xs[t >> 7][t & 127] = xm[(size_t)(j0 + (t >> 7)) * D + (t & 127)];
    __syncthreads();
    float a[16];
    #pragma unroll
    for (int e = 0; e < 16; e++) a[e] = 0.0f;
    #pragma unroll 4
    for (int k = 0; k < 128; k++) {
        float wv = root1[k * D + c];
        #pragma unroll
        for (int e = 0; e < 16; e++) a[e] += xs[e][k] * wv;
    }
    float bb = b1[c];
    #pragma unroll
    for (int e = 0; e < 16; e++) g_m1[(size_t)(j0 + e) * D + c] = fmaxf(a[e] + bb, 0.0f);
}

// ======================= kernel 3: ebase = x_e @ root1 + b1, 16 rows =========
__global__ void k_ebase(const float* __restrict__ xe, const float* __restrict__ root1,
                        const float* __restrict__ b1) {
    int i0 = blockIdx.x * 16;
    int c = threadIdx.x;
    __shared__ float xs[16][128];
    for (int t = c; t < 16 * 128; t += 128) xs[t >> 7][t & 127] = xe[(size_t)(i0 + (t >> 7)) * D + (t & 127)];
    __syncthreads();
    float a[16];
    #pragma unroll
    for (int e = 0; e < 16; e++) a[e] = 0.0f;
    #pragma unroll 4
    for (int k = 0; k < 128; k++) {
        float wv = root1[k * D + c];
        #pragma unroll
        for (int e = 0; e < 16; e++) a[e] += xs[e][k] * wv;
    }
    float bb = b1[c];
    #pragma unroll
    for (int e = 0; e < 16; e++) g_ebase[(size_t)(i0 + e) * D + c] = a[e] + bb;
}

// ======================= kernel 4: ZH[r][n][j] = fp16 K-major ================
__global__ void k_Z(const float* __restrict__ xm, const float* __restrict__ W1,
                    const float* __restrict__ W2) {
    int ri = blockIdx.y;
    int j0 = blockIdx.x * 16;
    __shared__ float xs[16][128], ms[16][128];
    for (int t = threadIdx.x; t < 16 * 128; t += 256) {
        int e = t >> 7, k = t & 127;
        xs[e][k] = xm[(size_t)(j0 + e) * D + k];
        ms[e][k] = g_m1[(size_t)(j0 + e) * D + k];
    }
    __syncthreads();
    int c = threadIdx.x;
    int cc = c & 127;
    const float* W = ((c < 128) ? W1 : W2) + (size_t)(ri + 1) * D * D;
    const float(*S)[128] = (c < 128) ? xs : ms;
    float a[16];
    #pragma unroll
    for (int e = 0; e < 16; e++) a[e] = 0.0f;
    #pragma unroll 4
    for (int k = 0; k < 128; k++) {
        float wv = W[k * D + cc];
        #pragma unroll
        for (int e = 0; e < 16; e++) a[e] += S[e][k] * wv;
    }
    __half2* dst = (__half2*)(g_ZH + ((size_t)ri * 256 + c) * NM + j0);
    #pragma unroll
    for (int e = 0; e < 8; e++) dst[e] = __floats2half2_rn(a[2 * e], a[2 * e + 1]);
}

// ======================= kernel 5: fp16 mask-GEMM, 64x64 warp tiles ==========
// grid (79, 4): x = M tile (128 rows), y = K quarter (2560). N = 256 full.
// 256 threads, 8 warps: wm = wid&1 (2 x 64 rows), wn = wid>>1 (4 x 64 cols).
constexpr int KT = 64;                         // fp16 K per tile
constexpr int KQ = 2560;
constexpr int ITERS = KQ / KT;                 // 40
constexpr int ASTR = 72;                       // halfs per smem row
constexpr int A_H = 128 * ASTR;                // 9216 halfs
constexpr int B_H = 256 * ASTR;                // 18432 halfs
constexpr int STAGE_H = A_H + B_H;             // 27648 halfs
constexpr int STAGE_B = STAGE_H * 2;           // 55296 bytes
constexpr int SM_MMA_BYTES = 2 * STAGE_B;      // 110592 bytes

__global__ __launch_bounds__(256, 1) void k_mma() {
    extern __shared__ __half smh[];
    uint32_t sbase = smem_u32(smh);

    int tid = threadIdx.x;
    int wid = tid >> 5, lane = tid & 31;
    int gid = lane >> 2, t4 = lane & 3;
    int wm = wid & 1, wn = wid >> 1;

    int i0 = blockIdx.x * 128;
    int kbase = blockIdx.y * KQ;

    // ---- A build role: 2 chunks of (row, 16 lev bytes) per thread ----
    int mrowA[2];
    const unsigned char* levrow[2];
    #pragma unroll
    for (int h = 0; h < 2; h++) {
        int c = tid + h * 256;
        mrowA[h] = c >> 2;
        int gr = min(i0 + mrowA[h], NE - 1);
        levrow[h] = g_lev + (size_t)gr * NM;
    }
    const __half* invrow0 = g_invh + (size_t)min(i0 + mrowA[0], NE - 1) * 8;
    const __half* invrow1 = g_invh + (size_t)min(i0 + mrowA[1], NE - 1) * 8;

    auto buildA = [&](int s, int r, int j0) {
        unsigned char rv = (unsigned char)(r + 1);
        #pragma unroll
        for (int h = 0; h < 2; h++) {
            int c = tid + h * 256;
            int row = c >> 2, aq = c & 3;
            uint4 u = *(const uint4*)(levrow[h] + j0 + aq * 16);
            unsigned char bts[16];
            *(uint4*)bts = u;
            __half ivh = (h == 0) ? invrow0[r + 1] : invrow1[r + 1];
            __half z = __ushort_as_half((unsigned short)0);
            uint32_t pk[8];
            #pragma unroll
            for (int q = 0; q < 8; q++) {
                __half2 h2;
                h2.x = (bts[2 * q] == rv) ? ivh : z;
                h2.y = (bts[2 * q + 1] == rv) ? ivh : z;
                pk[q] = *(uint32_t*)&h2;
            }
            uint32_t* dst = (uint32_t*)(smh + s * STAGE_H + row * ASTR + aq * 16);
            *(uint4*)dst = make_uint4(pk[0], pk[1], pk[2], pk[3]);
            *(uint4*)(dst + 4) = make_uint4(pk[4], pk[5], pk[6], pk[7]);
        }
    };
    auto stageB = [&](int s, int r, int j0) {
        uint32_t sb = sbase + s * STAGE_B + A_H * 2;
        const __half* gb = g_ZH + (size_t)r * 256 * NM + j0;
        #pragma unroll
        for (int h = 0; h < 8; h++) {
            int c = tid + h * 256;
            int n = c >> 3, ch = c & 7;
            uint32_t sa = sb + (uint32_t)(n * (ASTR * 2) + ch * 16);
            CP_ASYNC16(sa, gb + (size_t)n * NM + ch * 8);
        }
        CP_COMMIT();
    };

    // ---- ldmatrix lane base addresses (stage 0; stage 1 adds STAGE_B) ----
    uint32_t aAddr[4], bAddr[4];
    #pragma unroll
    for (int mi = 0; mi < 4; mi++) {
        int row = wm * 64 + mi * 16 + (lane & 15);
        aAddr[mi] = sbase + (uint32_t)(row * ASTR + (lane >> 4) * 8) * 2u;
    }
    #pragma unroll
    for (int nj = 0; nj < 4; nj++) {
        int nrow = wn * 64 + nj * 16 + ((lane >> 4) & 1) * 8 + (lane & 7);
        int koff = ((lane >> 3) & 1) * 8;
        bAddr[nj] = sbase + (uint32_t)(A_H * 2) + (uint32_t)(nrow * ASTR + koff) * 2u;
    }

    float dacc[4][8][4];
    #pragma unroll
    for (int mi = 0; mi < 4; mi++)
        #pragma unroll
        for (int ni = 0; ni < 8; ni++)
            #pragma unroll
            for (int q = 0; q < 4; q++) dacc[mi][ni][q] = 0.0f;

    {
        int kg = kbase;
        stageB(0, kg >> 11, kg & 2047);
        buildA(0, kg >> 11, kg & 2047);
    }

    for (int it = 0; it < ITERS; it++) {
        int s = it & 1;
        CP_WAIT0();
        __syncthreads();
        if (it + 1 < ITERS) {
            int kg = kbase + (it + 1) * KT;
            stageB(s ^ 1, kg >> 11, kg & 2047);
            buildA(s ^ 1, kg >> 11, kg & 2047);
        }

        uint32_t soff = (uint32_t)(s * STAGE_B);
        #pragma unroll
        for (int kk = 0; kk < 4; kk++) {
            uint32_t kb = soff + kk * 32;   // 16 halfs = 32 bytes
            uint32_t af[4][4], bf[8][2];
            #pragma unroll
            for (int mi = 0; mi < 4; mi++)
                LDSM_X4(af[mi][0], af[mi][1], af[mi][2], af[mi][3], aAddr[mi] + kb);
            #pragma unroll
            for (int nj = 0; nj < 4; nj++) {
                uint32_t r0, r1, r2, r3;
                LDSM_X4(r0, r1, r2, r3, bAddr[nj] + kb);
                bf[2 * nj][0] = r0;     bf[2 * nj][1] = r1;
                bf[2 * nj + 1][0] = r2; bf[2 * nj + 1][1] = r3;
            }
            #pragma unroll
            for (int mi = 0; mi < 4; mi++)
                #pragma unroll
                for (int ni = 0; ni < 8; ni++)
                    mma_f16(dacc[mi][ni], af[mi], bf[ni]);
        }
        __syncthreads();
    }

    // ---- epilogue: write partials ----
    float* dst = g_part + (size_t)blockIdx.y * NEP * 256;
    #pragma unroll
    for (int mi = 0; mi < 4; mi++) {
        int r0 = i0 + wm * 64 + mi * 16 + gid;
        #pragma unroll
        for (int ni = 0; ni < 8; ni++) {
            int cn = wn * 64 + ni * 8 + 2 * t4;
            *(float2*)(dst + (size_t)r0 * 256 + cn) = make_float2(dacc[mi][ni][0], dacc[mi][ni][1]);
            *(float2*)(dst + (size_t)(r0 + 8) * 256 + cn) = make_float2(dacc[mi][ni][2], dacc[mi][ni][3]);
        }
    }
}

// ======================= kernel 6: reduce 4 partials + both conv epilogues ===
constexpr int SM_EPI_BYTES = 64 * 132 * 4;
__global__ __launch_bounds__(256, 1) void k_epi(const float* __restrict__ root2,
                                                const float* __restrict__ b2,
                                                float* __restrict__ out) {
    extern __shared__ float sE1[];   // [64][132]
    int i0 = blockIdx.x * 64;
    int tid = threadIdx.x;

    for (int idx = tid; idx < 64 * 32; idx += 256) {
        int e = idx >> 5, q = idx & 31;
        int i = i0 + e;
        float4 v = make_float4(0, 0, 0, 0);
        if (i < NE) {
            float4 s = *(const float4*)(g_ebase + (size_t)i * D + q * 4);
            #pragma unroll
            for (int z = 0; z < 4; z++) {
                float4 p = *(const float4*)(g_part + ((size_t)z * NEP + i) * 256 + q * 4);
                s.x += p.x; s.y += p.y; s.z += p.z; s.w += p.w;
            }
            v.x = fmaxf(s.x, 0.0f); v.y = fmaxf(s.y, 0.0f);
            v.z = fmaxf(s.z, 0.0f); v.w = fmaxf(s.w, 0.0f);
        }
        *(float4*)(sE1 + e * 132 + q * 4) = v;
    }
    __syncthreads();

    int pe = tid >> 3, cg = tid & 7;
    int eA = pe * 2, eB = pe * 2 + 1;
    int iA = i0 + eA, iB = i0 + eB;
    int c0 = cg * 16;
    float4 oA[4], oB[4];
    #pragma unroll
    for (int q = 0; q < 4; q++) {
        float4 bb = *(const float4*)(b2 + c0 + q * 4);
        float4 gA = make_float4(0, 0, 0, 0), gB = make_float4(0, 0, 0, 0);
        #pragma unroll
        for (int z = 0; z < 4; z++) {
            if (iA < NE) {
                float4 p = *(const float4*)(g_part + ((size_t)z * NEP + iA) * 256 + 128 + c0 + q * 4);
                gA.x += p.x; gA.y += p.y; gA.z += p.z; gA.w += p.w;
            }
            if (iB < NE) {
                float4 p = *(const float4*)(g_part + ((size_t)z * NEP + iB) * 256 + 128 + c0 + q * 4);
                gB.x += p.x; gB.y += p.y; gB.z += p.z; gB.w += p.w;
            }
        }
        oA[q] = make_float4(bb.x + gA.x, bb.y + gA.y, bb.z + gA.z, bb.w + gA.w);
        oB[q] = make_float4(bb.x + gB.x, bb.y + gB.y, bb.z + gB.z, bb.w + gB.w);
    }
    #pragma unroll 4
    for (int kk = 0; kk < 128; kk++) {
        float evA = sE1[eA * 132 + kk];
        float evB = sE1[eB * 132 + kk];
        const float4* r2 = (const float4*)(root2 + kk * D + c0);
        #pragma unroll
        for (int q = 0; q < 4; q++) {
            float4 r = r2[q];
            oA[q].x += evA * r.x; oA[q].y += evA * r.y; oA[q].z += evA * r.z; oA[q].w += evA * r.w;
            oB[q].x += evB * r.x; oB[q].y += evB * r.y; oB[q].z += evB * r.z; oB[q].w += evB * r.w;
        }
    }
    if (iA < NE) {
        #pragma unroll
        for (int q = 0; q < 4; q++) *(float4*)(out + (size_t)iA * D + c0 + q * 4) = oA[q];
    }
    if (iB < NE) {
        #pragma unroll
        for (int q = 0; q < 4; q++) *(float4*)(out + (size_t)iB * D + c0 + q * 4) = oB[q];
    }
}

// ======================= launch =======================
extern "C" void kernel_launch(void* const* d_in, const int* in_sizes, int n_in,
                              void* d_out, int out_size) {
    const float* xe    = (const float*)d_in[0];
    const float* xm    = (const float*)d_in[1];
    const float* w     = (const float*)d_in[2];
    const float* W1    = (const float*)d_in[3];
    const float* root1 = (const float*)d_in[4];
    const float* b1    = (const float*)d_in[5];
    const float* W2    = (const float*)d_in[6];
    const float* root2 = (const float*)d_in[7];
    const float* b2    = (const float*)d_in[8];
    float* out = (float*)d_out;

    k_lev<<<NE, 256>>>(w);
    k_m1<<<NM / 16, 128>>>(xm, root1, b1);
    k_ebase<<<NE / 16, 128>>>(xe, root1, b1);
    k_Z<<<dim3(NM / 16, 5), 256>>>(xm, W1, W2);

    cudaFuncSetAttribute(k_mma, cudaFuncAttributeMaxDynamicSharedMemorySize, SM_MMA_BYTES);
    k_mma<<<dim3(79, 4), 256, SM_MMA_BYTES>>>();

    cudaFuncSetAttribute(k_epi, cudaFuncAttributeMaxDynamicSharedMemorySize, SM_EPI_BYTES);
    k_epi<<<(NE + 63) / 64, 256, SM_EPI_BYTES>>>(root2, b2, out);
}

// round 10
// speedup vs baseline: 3.7505x; 1.0093x over previous
#include <cuda_runtime.h>
#include <cuda_fp16.h>
#include <cstdint>

#define NE 10000
#define NM 2048
#define D  128
#define NEP 10112            // 79*128 padded entity count
#define KSPLIT 8

// ======================= device scratch (no allocations allowed) ============
__device__ unsigned char g_lev[(size_t)NE * NM];   // 0 = no edge, 1..5 relation
__device__ __half g_invh[NE * 8];                  // [i][r] 1/cnt (fp16), r=0 -> 0
__device__ float g_m1[NM * D];                     // relu(x_m @ root1 + b1)
__device__ __half g_ZH[(size_t)5 * 256 * NM];      // [r][n][j] K-major fp16 B
__device__ float g_ebase[(size_t)NE * D];          // x_e @ root1 + b1
__device__ float g_part[(size_t)KSPLIT * NEP * 256];  // K-split partials

// ======================= small PTX helpers ============
#define CP_ASYNC16(s, g) asm volatile("cp.async.cg.shared.global [%0], [%1], 16;" :: "r"(s), "l"(g))
#define CP_COMMIT()      asm volatile("cp.async.commit_group;" ::: "memory")
#define CP_WAIT0()       asm volatile("cp.async.wait_group 0;" ::: "memory")
#define LDSM_X4(r0, r1, r2, r3, a)                                                   \
    asm volatile("ldmatrix.sync.aligned.m8n8.x4.shared.b16 {%0,%1,%2,%3}, [%4];"     \
                 : "=r"(r0), "=r"(r1), "=r"(r2), "=r"(r3) : "r"(a))

__device__ __forceinline__ uint32_t smem_u32(const void* p) {
    uint32_t a;
    asm("{ .reg .u64 t; cvta.to.shared.u64 t, %1; cvt.u32.u64 %0, t; }" : "=r"(a) : "l"(p));
    return a;
}

// fp16-accumulate HMMA
__device__ __forceinline__ void mma_f16h(uint32_t* d, const uint32_t* a, uint32_t b0, uint32_t b1) {
    asm volatile(
        "mma.sync.aligned.m16n8k16.row.col.f16.f16.f16.f16 "
        "{%0,%1}, {%2,%3,%4,%5}, {%6,%7}, {%0,%1};"
        : "+r"(d[0]), "+r"(d[1])
        : "r"(a[0]), "r"(a[1]), "r"(a[2]), "r"(a[3]), "r"(b0), "r"(b1));
}

// ======================= kernel 1: levels + inverse counts (fp16) ============
__global__ void k_lev(const float* __restrict__ w) {
    int i = blockIdx.x;
    __shared__ int scnt[5];
    if (threadIdx.x < 5) scnt[threadIdx.x] = 0;
    __syncthreads();
    int cnt[5] = {0, 0, 0, 0, 0};
    const float* wr = w + (size_t)i * NM;
    unsigned char* lr = g_lev + (size_t)i * NM;
    #pragma unroll
    for (int s = 0; s < 8; s++) {
        int j = threadIdx.x + s * 256;
        float v = wr[j];
        int lv = (int)ceilf(v * 6.0f) - 1;
        int o = (lv >= 1 && lv <= 5) ? lv : 0;
        lr[j] = (unsigned char)o;
        if (o) cnt[o - 1]++;
    }
    #pragma unroll
    for (int r = 0; r < 5; r++) {
        int v = cnt[r];
        #pragma unroll
        for (int off = 16; off; off >>= 1) v += __shfl_down_sync(0xffffffffu, v, off);
        if ((threadIdx.x & 31) == 0) atomicAdd(&scnt[r], v);
    }
    __syncthreads();
    if (threadIdx.x < 8) {
        float iv = 0.0f;
        if (threadIdx.x >= 1 && threadIdx.x <= 5) {
            int c = scnt[threadIdx.x - 1];
            iv = (c > 0) ? 1.0f / (float)c : 0.0f;
        }
        g_invh[i * 8 + threadIdx.x] = __float2half(iv);
    }
}

// ======================= kernel 2: root1 transform for moles AND entities ====
// blocks [0, NM/16): m1 = relu(x_m@root1+b1); blocks [NM/16, +NE/16): ebase.
__global__ void k_root1(const float* __restrict__ xm, const float* __restrict__ xe,
                        const float* __restrict__ root1, const float* __restrict__ b1) {
    __shared__ float xs[128][20];
    int bi = blockIdx.x;
    bool mole = bi < (NM / 16);
    int r0 = mole ? bi * 16 : (bi - NM / 16) * 16;
    const float* src = (mole ? xm : xe) + (size_t)r0 * D;
    int c = threadIdx.x;
    for (int t = c; t < 16 * 128; t += 128) {
        int e = t >> 7, k = t & 127;
        xs[k][e] = src[e * D + k];
    }
    __syncthreads();
    float a[16];
    #pragma unroll
    for (int e = 0; e < 16; e++) a[e] = 0.0f;
    #pragma unroll 2
    for (int k = 0; k < 128; k++) {
        float wv = root1[k * D + c];
        float4 x0 = *(const float4*)&xs[k][0];
        float4 x1 = *(const float4*)&xs[k][4];
        float4 x2 = *(const float4*)&xs[k][8];
        float4 x3 = *(const float4*)&xs[k][12];
        a[0] += x0.x * wv; a[1] += x0.y * wv; a[2] += x0.z * wv; a[3] += x0.w * wv;
        a[4] += x1.x * wv; a[5] += x1.y * wv; a[6] += x1.z * wv; a[7] += x1.w * wv;
        a[8] += x2.x * wv; a[9] += x2.y * wv; a[10] += x2.z * wv; a[11] += x2.w * wv;
        a[12] += x3.x * wv; a[13] += x3.y * wv; a[14] += x3.z * wv; a[15] += x3.w * wv;
    }
    float bb = b1[c];
    if (mole) {
        #pragma unroll
        for (int e = 0; e < 16; e++) g_m1[(size_t)(r0 + e) * D + c] = fmaxf(a[e] + bb, 0.0f);
    } else {
        #pragma unroll
        for (int e = 0; e < 16; e++) g_ebase[(size_t)(r0 + e) * D + c] = a[e] + bb;
    }
}

// ======================= kernel 4: ZH[r][n][j] = fp16 K-major ================
__global__ void k_Z(const float* __restrict__ xm, const float* __restrict__ W1,
                    const float* __restrict__ W2) {
    __shared__ float xs[128][20], ms[128][20];
    int ri = blockIdx.y;
    int j0 = blockIdx.x * 16;
    for (int t = threadIdx.x; t < 16 * 128; t += 256) {
        int e = t >> 7, k = t & 127;
        xs[k][e] = xm[(size_t)(j0 + e) * D + k];
        ms[k][e] = g_m1[(size_t)(j0 + e) * D + k];
    }
    __syncthreads();
    int c = threadIdx.x;
    int cc = c & 127;
    const float* W = ((c < 128) ? W1 : W2) + (size_t)(ri + 1) * D * D;
    const float(*S)[20] = (c < 128) ? xs : ms;
    float a[16];
    #pragma unroll
    for (int e = 0; e < 16; e++) a[e] = 0.0f;
    #pragma unroll 2
    for (int k = 0; k < 128; k++) {
        float wv = W[k * D + cc];
        float4 x0 = *(const float4*)&S[k][0];
        float4 x1 = *(const float4*)&S[k][4];
        float4 x2 = *(const float4*)&S[k][8];
        float4 x3 = *(const float4*)&S[k][12];
        a[0] += x0.x * wv; a[1] += x0.y * wv; a[2] += x0.z * wv; a[3] += x0.w * wv;
        a[4] += x1.x * wv; a[5] += x1.y * wv; a[6] += x1.z * wv; a[7] += x1.w * wv;
        a[8] += x2.x * wv; a[9] += x2.y * wv; a[10] += x2.z * wv; a[11] += x2.w * wv;
        a[12] += x3.x * wv; a[13] += x3.y * wv; a[14] += x3.z * wv; a[15] += x3.w * wv;
    }
    __half2* dst = (__half2*)(g_ZH + ((size_t)ri * 256 + c) * NM + j0);
    #pragma unroll
    for (int e = 0; e < 8; e++) dst[e] = __floats2half2_rn(a[2 * e], a[2 * e + 1]);
}

// ======================= kernel 5: fp16 mask-GEMM, 64x64 warp tiles ==========
// grid (79, 8): x = M tile (128 rows), y = K eighth (1280). N = 256 full.
constexpr int KT = 64;
constexpr int KQ = 10240 / KSPLIT;             // 1280
constexpr int ITERS = KQ / KT;                 // 20
constexpr int ASTR = 72;
constexpr int A_H = 128 * ASTR;
constexpr int B_H = 256 * ASTR;
constexpr int STAGE_H = A_H + B_H;
constexpr int STAGE_B = STAGE_H * 2;
constexpr int SM_MMA_BYTES = 2 * STAGE_B;      // 110592 bytes

__global__ __launch_bounds__(256, 1) void k_mma() {
    extern __shared__ __half smh[];
    uint32_t sbase = smem_u32(smh);

    int tid = threadIdx.x;
    int wid = tid >> 5, lane = tid & 31;
    int gid = lane >> 2, t4 = lane & 3;
    int wm = wid & 1, wn = wid >> 1;

    int i0 = blockIdx.x * 128;
    int kbase = blockIdx.y * KQ;

    int mrowA[2];
    const unsigned char* levrow[2];
    #pragma unroll
    for (int h = 0; h < 2; h++) {
        int c = tid + h * 256;
        mrowA[h] = c >> 2;
        int gr = min(i0 + mrowA[h], NE - 1);
        levrow[h] = g_lev + (size_t)gr * NM;
    }
    const __half* invrow0 = g_invh + (size_t)min(i0 + mrowA[0], NE - 1) * 8;
    const __half* invrow1 = g_invh + (size_t)min(i0 + mrowA[1], NE - 1) * 8;

    auto buildA = [&](int s, int r, int j0) {
        unsigned char rv = (unsigned char)(r + 1);
        #pragma unroll
        for (int h = 0; h < 2; h++) {
            int c = tid + h * 256;
            int row = c >> 2, aq = c & 3;
            uint4 u = *(const uint4*)(levrow[h] + j0 + aq * 16);
            unsigned char bts[16];
            *(uint4*)bts = u;
            __half ivh = (h == 0) ? invrow0[r + 1] : invrow1[r + 1];
            __half z = __ushort_as_half((unsigned short)0);
            uint32_t pk[8];
            #pragma unroll
            for (int q = 0; q < 8; q++) {
                __half2 h2;
                h2.x = (bts[2 * q] == rv) ? ivh : z;
                h2.y = (bts[2 * q + 1] == rv) ? ivh : z;
                pk[q] = *(uint32_t*)&h2;
            }
            uint32_t* dst = (uint32_t*)(smh + s * STAGE_H + row * ASTR + aq * 16);
            *(uint4*)dst = make_uint4(pk[0], pk[1], pk[2], pk[3]);
            *(uint4*)(dst + 4) = make_uint4(pk[4], pk[5], pk[6], pk[7]);
        }
    };
    auto stageB = [&](int s, int r, int j0) {
        uint32_t sb = sbase + s * STAGE_B + A_H * 2;
        const __half* gb = g_ZH + (size_t)r * 256 * NM + j0;
        #pragma unroll
        for (int h = 0; h < 8; h++) {
            int c = tid + h * 256;
            int n = c >> 3, ch = c & 7;
            uint32_t sa = sb + (uint32_t)(n * (ASTR * 2) + ch * 16);
            CP_ASYNC16(sa, gb + (size_t)n * NM + ch * 8);
        }
        CP_COMMIT();
    };

    uint32_t aAddr[4], bAddr[4];
    #pragma unroll
    for (int mi = 0; mi < 4; mi++) {
        int row = wm * 64 + mi * 16 + (lane & 15);
        aAddr[mi] = sbase + (uint32_t)(row * ASTR + (lane >> 4) * 8) * 2u;
    }
    #pragma unroll
    for (int nj = 0; nj < 4; nj++) {
        int nrow = wn * 64 + nj * 16 + ((lane >> 4) & 1) * 8 + (lane & 7);
        int koff = ((lane >> 3) & 1) * 8;
        bAddr[nj] = sbase + (uint32_t)(A_H * 2) + (uint32_t)(nrow * ASTR + koff) * 2u;
    }

    float dacc[4][8][4];
    uint32_t hacc[4][8][2];
    #pragma unroll
    for (int mi = 0; mi < 4; mi++)
        #pragma unroll
        for (int ni = 0; ni < 8; ni++) {
            dacc[mi][ni][0] = dacc[mi][ni][1] = dacc[mi][ni][2] = dacc[mi][ni][3] = 0.0f;
            hacc[mi][ni][0] = hacc[mi][ni][1] = 0u;
        }

    {
        int kg = kbase;
        stageB(0, kg >> 11, kg & 2047);
        buildA(0, kg >> 11, kg & 2047);
    }

    for (int it = 0; it < ITERS; it++) {
        int s = it & 1;
        CP_WAIT0();
        __syncthreads();
        if (it + 1 < ITERS) {
            int kg = kbase + (it + 1) * KT;
            stageB(s ^ 1, kg >> 11, kg & 2047);
            buildA(s ^ 1, kg >> 11, kg & 2047);
        }

        uint32_t soff = (uint32_t)(s * STAGE_B);
        #pragma unroll
        for (int kk = 0; kk < 4; kk++) {
            uint32_t kb = soff + kk * 32;
            uint32_t af[4][4];
            #pragma unroll
            for (int mi = 0; mi < 4; mi++)
                LDSM_X4(af[mi][0], af[mi][1], af[mi][2], af[mi][3], aAddr[mi] + kb);
            #pragma unroll
            for (int nj = 0; nj < 4; nj++) {
                uint32_t r0, r1, r2, r3;
                LDSM_X4(r0, r1, r2, r3, bAddr[nj] + kb);
                #pragma unroll
                for (int mi = 0; mi < 4; mi++) {
                    mma_f16h(hacc[mi][2 * nj], af[mi], r0, r1);
                    mma_f16h(hacc[mi][2 * nj + 1], af[mi], r2, r3);
                }
            }
        }
        // drain fp16 window into fp32 accumulators every iter (K=64 window)
        #pragma unroll
        for (int mi = 0; mi < 4; mi++)
            #pragma unroll
            for (int ni = 0; ni < 8; ni++) {
                float2 lo = __half22float2(*(__half2*)&hacc[mi][ni][0]);
                float2 hi = __half22float2(*(__half2*)&hacc[mi][ni][1]);
                dacc[mi][ni][0] += lo.x; dacc[mi][ni][1] += lo.y;
                dacc[mi][ni][2] += hi.x; dacc[mi][ni][3] += hi.y;
                hacc[mi][ni][0] = 0u; hacc[mi][ni][1] = 0u;
            }
        __syncthreads();
    }

    float* dst = g_part + (size_t)blockIdx.y * NEP * 256;
    #pragma unroll
    for (int mi = 0; mi < 4; mi++) {
        int r0 = i0 + wm * 64 + mi * 16 + gid;
        #pragma unroll
        for (int ni = 0; ni < 8; ni++) {
            int cn = wn * 64 + ni * 8 + 2 * t4;
            *(float2*)(dst + (size_t)r0 * 256 + cn) = make_float2(dacc[mi][ni][0], dacc[mi][ni][1]);
            *(float2*)(dst + (size_t)(r0 + 8) * 256 + cn) = make_float2(dacc[mi][ni][2], dacc[mi][ni][3]);
        }
    }
}

// ======================= kernel 6: reduce partials + both conv epilogues =====
constexpr int SM_EPI_BYTES = 64 * 132 * 4;
__global__ __launch_bounds__(256, 1) void k_epi(const float* __restrict__ root2,
                                                const float* __restrict__ b2,
                                                float* __restrict__ out) {
    extern __shared__ float sE1[];   // [64][132]
    int i0 = blockIdx.x * 64;
    int tid = threadIdx.x;

    for (int idx = tid; idx < 64 * 32; idx += 256) {
        int e = idx >> 5, q = idx & 31;
        int i = i0 + e;
        float4 v = make_float4(0, 0, 0, 0);
        if (i < NE) {
            float4 s = *(const float4*)(g_ebase + (size_t)i * D + q * 4);
            #pragma unroll
            for (int z = 0; z < KSPLIT; z++) {
                float4 p = *(const float4*)(g_part + ((size_t)z * NEP + i) * 256 + q * 4);
                s.x += p.x; s.y += p.y; s.z += p.z; s.w += p.w;
            }
            v.x = fmaxf(s.x, 0.0f); v.y = fmaxf(s.y, 0.0f);
            v.z = fmaxf(s.z, 0.0f); v.w = fmaxf(s.w, 0.0f);
        }
        *(float4*)(sE1 + e * 132 + q * 4) = v;
    }
    __syncthreads();

    int pe = tid >> 3, cg = tid & 7;
    int eA = pe * 2, eB = pe * 2 + 1;
    int iA = i0 + eA, iB = i0 + eB;
    int c0 = cg * 16;
    float4 oA[4], oB[4];
    #pragma unroll
    for (int q = 0; q < 4; q++) {
        float4 bb = *(const float4*)(b2 + c0 + q * 4);
        float4 gA = make_float4(0, 0, 0, 0), gB = make_float4(0, 0, 0, 0);
        #pragma unroll
        for (int z = 0; z < KSPLIT; z++) {
            if (iA < NE) {
                float4 p = *(const float4*)(g_part + ((size_t)z * NEP + iA) * 256 + 128 + c0 + q * 4);
                gA.x += p.x; gA.y += p.y; gA.z += p.z; gA.w += p.w;
            }
            if (iB < NE) {
                float4 p = *(const float4*)(g_part + ((size_t)z * NEP + iB) * 256 + 128 + c0 + q * 4);
                gB.x += p.x; gB.y += p.y; gB.z += p.z; gB.w += p.w;
            }
        }
        oA[q] = make_float4(bb.x + gA.x, bb.y + gA.y, bb.z + gA.z, bb.w + gA.w);
        oB[q] = make_float4(bb.x + gB.x, bb.y + gB.y, bb.z + gB.z, bb.w + gB.w);
    }
    #pragma unroll 4
    for (int kk = 0; kk < 128; kk++) {
        float evA = sE1[eA * 132 + kk];
        float evB = sE1[eB * 132 + kk];
        const float4* r2 = (const float4*)(root2 + kk * D + c0);
        #pragma unroll
        for (int q = 0; q < 4; q++) {
            float4 r = r2[q];
            oA[q].x += evA * r.x; oA[q].y += evA * r.y; oA[q].z += evA * r.z; oA[q].w += evA * r.w;
            oB[q].x += evB * r.x; oB[q].y += evB * r.y; oB[q].z += evB * r.z; oB[q].w += evB * r.w;
        }
    }
    if (iA < NE) {
        #pragma unroll
        for (int q = 0; q < 4; q++) *(float4*)(out + (size_t)iA * D + c0 + q * 4) = oA[q];
    }
    if (iB < NE) {
        #pragma unroll
        for (int q = 0; q < 4; q++) *(float4*)(out + (size_t)iB * D + c0 + q * 4) = oB[q];
    }
}

// ======================= launch =======================
extern "C" void kernel_launch(void* const* d_in, const int* in_sizes, int n_in,
                              void* d_out, int out_size) {
    const float* xe    = (const float*)d_in[0];
    const float* xm    = (const float*)d_in[1];
    const float* w     = (const float*)d_in[2];
    const float* W1    = (const float*)d_in[3];
    const float* root1 = (const float*)d_in[4];
    const float* b1    = (const float*)d_in[5];
    const float* W2    = (const float*)d_in[6];
    const float* root2 = (const float*)d_in[7];
    const float* b2    = (const float*)d_in[8];
    float* out = (float*)d_out;

    k_lev<<<NE, 256>>>(w);
    k_root1<<<NM / 16 + NE / 16, 128>>>(xm, xe, root1, b1);
    k_Z<<<dim3(NM / 16, 5), 256>>>(xm, W1, W2);

    cudaFuncSetAttribute(k_mma, cudaFuncAttributeMaxDynamicSharedMemorySize, SM_MMA_BYTES);
    k_mma<<<dim3(79, KSPLIT), 256, SM_MMA_BYTES>>>();

    cudaFuncSetAttribute(k_epi, cudaFuncAttributeMaxDynamicSharedMemorySize, SM_EPI_BYTES);
    k_epi<<<(NE + 63) / 64, 256, SM_EPI_BYTES>>>(root2, b2, out);
}

// round 11
// speedup vs baseline: 4.3586x; 1.1622x over previous
#include <cuda_runtime.h>
#include <cuda_fp16.h>
#include <cstdint>

#define NE 10000
#define NM 2048
#define D  128
#define NEP 10112            // 79*128 padded entity count
#define KSPLIT 4

// ======================= device scratch (no allocations allowed) ============
__device__ unsigned char g_lev[(size_t)NE * NM];   // 0 = no edge, 1..5 relation
__device__ __half g_invh[NE * 8];                  // [i][r] 1/cnt (fp16), r=0 -> 0
__device__ float g_m1[NM * D];                     // relu(x_m @ root1 + b1)
__device__ __half g_ZH[(size_t)5 * 256 * NM];      // [r][n][j] K-major fp16 B
__device__ float g_ebase[(size_t)NE * D];          // x_e @ root1 + b1
__device__ float g_part[(size_t)KSPLIT * NEP * 256];  // K-split partials

// ======================= small PTX helpers ============
#define CP_ASYNC16(s, g) asm volatile("cp.async.cg.shared.global [%0], [%1], 16;" :: "r"(s), "l"(g))
#define CP_COMMIT()      asm volatile("cp.async.commit_group;" ::: "memory")
#define CP_WAIT0()       asm volatile("cp.async.wait_group 0;" ::: "memory")
#define LDSM_X4(r0, r1, r2, r3, a)                                                   \
    asm volatile("ldmatrix.sync.aligned.m8n8.x4.shared.b16 {%0,%1,%2,%3}, [%4];"     \
                 : "=r"(r0), "=r"(r1), "=r"(r2), "=r"(r3) : "r"(a))

__device__ __forceinline__ uint32_t smem_u32(const void* p) {
    uint32_t a;
    asm("{ .reg .u64 t; cvta.to.shared.u64 t, %1; cvt.u32.u64 %0, t; }" : "=r"(a) : "l"(p));
    return a;
}

__device__ __forceinline__ void mma_f16(float* d, const uint32_t* a, uint32_t b0, uint32_t b1) {
    asm volatile(
        "mma.sync.aligned.m16n8k16.row.col.f32.f16.f16.f32 "
        "{%0,%1,%2,%3}, {%4,%5,%6,%7}, {%8,%9}, {%0,%1,%2,%3};"
        : "+f"(d[0]), "+f"(d[1]), "+f"(d[2]), "+f"(d[3])
        : "r"(a[0]), "r"(a[1]), "r"(a[2]), "r"(a[3]), "r"(b0), "r"(b1));
}

// ======================= kernel 1: levels + inverse counts (fp16) ============
__global__ void k_lev(const float* __restrict__ w) {
    int i = blockIdx.x;
    __shared__ int scnt[5];
    if (threadIdx.x < 5) scnt[threadIdx.x] = 0;
    __syncthreads();
    int cnt[5] = {0, 0, 0, 0, 0};
    const float* wr = w + (size_t)i * NM;
    unsigned char* lr = g_lev + (size_t)i * NM;
    #pragma unroll
    for (int s = 0; s < 8; s++) {
        int j = threadIdx.x + s * 256;
        float v = wr[j];
        int lv = (int)ceilf(v * 6.0f) - 1;
        int o = (lv >= 1 && lv <= 5) ? lv : 0;
        lr[j] = (unsigned char)o;
        if (o) cnt[o - 1]++;
    }
    #pragma unroll
    for (int r = 0; r < 5; r++) {
        int v = cnt[r];
        #pragma unroll
        for (int off = 16; off; off >>= 1) v += __shfl_down_sync(0xffffffffu, v, off);
        if ((threadIdx.x & 31) == 0) atomicAdd(&scnt[r], v);
    }
    __syncthreads();
    if (threadIdx.x < 8) {
        float iv = 0.0f;
        if (threadIdx.x >= 1 && threadIdx.x <= 5) {
            int c = scnt[threadIdx.x - 1];
            iv = (c > 0) ? 1.0f / (float)c : 0.0f;
        }
        g_invh[i * 8 + threadIdx.x] = __float2half(iv);
    }
}

// ======================= kernel 2: root1 transform (moles + entities) ========
__global__ void k_root1(const float* __restrict__ xm, const float* __restrict__ xe,
                        const float* __restrict__ root1, const float* __restrict__ b1) {
    __shared__ float xs[128][20];
    int bi = blockIdx.x;
    bool mole = bi < (NM / 16);
    int r0 = mole ? bi * 16 : (bi - NM / 16) * 16;
    const float* src = (mole ? xm : xe) + (size_t)r0 * D;
    int c = threadIdx.x;
    for (int t = c; t < 16 * 128; t += 128) {
        int e = t >> 7, k = t & 127;
        xs[k][e] = src[e * D + k];
    }
    __syncthreads();
    float a[16];
    #pragma unroll
    for (int e = 0; e < 16; e++) a[e] = 0.0f;
    #pragma unroll 2
    for (int k = 0; k < 128; k++) {
        float wv = root1[k * D + c];
        float4 x0 = *(const float4*)&xs[k][0];
        float4 x1 = *(const float4*)&xs[k][4];
        float4 x2 = *(const float4*)&xs[k][8];
        float4 x3 = *(const float4*)&xs[k][12];
        a[0] += x0.x * wv; a[1] += x0.y * wv; a[2] += x0.z * wv; a[3] += x0.w * wv;
        a[4] += x1.x * wv; a[5] += x1.y * wv; a[6] += x1.z * wv; a[7] += x1.w * wv;
        a[8] += x2.x * wv; a[9] += x2.y * wv; a[10] += x2.z * wv; a[11] += x2.w * wv;
        a[12] += x3.x * wv; a[13] += x3.y * wv; a[14] += x3.z * wv; a[15] += x3.w * wv;
    }
    float bb = b1[c];
    if (mole) {
        #pragma unroll
        for (int e = 0; e < 16; e++) g_m1[(size_t)(r0 + e) * D + c] = fmaxf(a[e] + bb, 0.0f);
    } else {
        #pragma unroll
        for (int e = 0; e < 16; e++) g_ebase[(size_t)(r0 + e) * D + c] = a[e] + bb;
    }
}

// ======================= kernel 4: ZH[r][n][j] = fp16 K-major ================
__global__ void k_Z(const float* __restrict__ xm, const float* __restrict__ W1,
                    const float* __restrict__ W2) {
    __shared__ float xs[128][20], ms[128][20];
    int ri = blockIdx.y;
    int j0 = blockIdx.x * 16;
    for (int t = threadIdx.x; t < 16 * 128; t += 256) {
        int e = t >> 7, k = t & 127;
        xs[k][e] = xm[(size_t)(j0 + e) * D + k];
        ms[k][e] = g_m1[(size_t)(j0 + e) * D + k];
    }
    __syncthreads();
    int c = threadIdx.x;
    int cc = c & 127;
    const float* W = ((c < 128) ? W1 : W2) + (size_t)(ri + 1) * D * D;
    const float(*S)[20] = (c < 128) ? xs : ms;
    float a[16];
    #pragma unroll
    for (int e = 0; e < 16; e++) a[e] = 0.0f;
    #pragma unroll 2
    for (int k = 0; k < 128; k++) {
        float wv = W[k * D + cc];
        float4 x0 = *(const float4*)&S[k][0];
        float4 x1 = *(const float4*)&S[k][4];
        float4 x2 = *(const float4*)&S[k][8];
        float4 x3 = *(const float4*)&S[k][12];
        a[0] += x0.x * wv; a[1] += x0.y * wv; a[2] += x0.z * wv; a[3] += x0.w * wv;
        a[4] += x1.x * wv; a[5] += x1.y * wv; a[6] += x1.z * wv; a[7] += x1.w * wv;
        a[8] += x2.x * wv; a[9] += x2.y * wv; a[10] += x2.z * wv; a[11] += x2.w * wv;
        a[12] += x3.x * wv; a[13] += x3.y * wv; a[14] += x3.z * wv; a[15] += x3.w * wv;
    }
    __half2* dst = (__half2*)(g_ZH + ((size_t)ri * 256 + c) * NM + j0);
    #pragma unroll
    for (int e = 0; e < 8; e++) dst[e] = __floats2half2_rn(a[2 * e], a[2 * e + 1]);
}

// ======================= kernel 5: fp16 mask-GEMM, 64x32 warp tiles ==========
// grid (79, 2, 4): x = M tile (128), y = N half (128), z = K quarter (2560).
// 256 threads, 8 warps: wm = wid&1 (2 x 64 rows), wn = wid>>1 (4 x 32 cols).
// 2 CTAs per SM (regs <= 128, smem 72KB/CTA).
constexpr int KT = 64;
constexpr int KQ = 10240 / KSPLIT;             // 2560
constexpr int ITERS = KQ / KT;                 // 40
constexpr int ASTR = 72;
constexpr int A_H = 128 * ASTR;                // 9216 halfs
constexpr int B_H = 128 * ASTR;                // 9216 halfs
constexpr int STAGE_H = A_H + B_H;             // 18432 halfs
constexpr int STAGE_B = STAGE_H * 2;           // 36864 bytes
constexpr int SM_MMA_BYTES = 2 * STAGE_B;      // 73728 bytes

__global__ __launch_bounds__(256, 2) void k_mma() {
    extern __shared__ __half smh[];
    uint32_t sbase = smem_u32(smh);

    int tid = threadIdx.x;
    int wid = tid >> 5, lane = tid & 31;
    int gid = lane >> 2, t4 = lane & 3;
    int wm = wid & 1, wn = wid >> 1;

    int i0 = blockIdx.x * 128;
    int n0g = blockIdx.y * 128;
    int kbase = blockIdx.z * KQ;

    // A-build role: 2 chunks of (row = c>>2, 16 lev bytes at chunk aq = c&3)
    int mrowA[2];
    const unsigned char* levrow[2];
    #pragma unroll
    for (int h = 0; h < 2; h++) {
        int c = tid + h * 256;
        mrowA[h] = c >> 2;
        int gr = min(i0 + mrowA[h], NE - 1);
        levrow[h] = g_lev + (size_t)gr * NM;
    }
    const __half* invrow0 = g_invh + (size_t)min(i0 + mrowA[0], NE - 1) * 8;
    const __half* invrow1 = g_invh + (size_t)min(i0 + mrowA[1], NE - 1) * 8;

    auto buildA = [&](int s, int r, int j0) {
        unsigned char rv = (unsigned char)(r + 1);
        #pragma unroll
        for (int h = 0; h < 2; h++) {
            int c = tid + h * 256;
            int row = c >> 2, aq = c & 3;
            uint4 u = *(const uint4*)(levrow[h] + j0 + aq * 16);
            unsigned char bts[16];
            *(uint4*)bts = u;
            __half ivh = (h == 0) ? invrow0[r + 1] : invrow1[r + 1];
            __half z = __ushort_as_half((unsigned short)0);
            uint32_t pk[8];
            #pragma unroll
            for (int q = 0; q < 8; q++) {
                __half2 h2;
                h2.x = (bts[2 * q] == rv) ? ivh : z;
                h2.y = (bts[2 * q + 1] == rv) ? ivh : z;
                pk[q] = *(uint32_t*)&h2;
            }
            uint32_t* dst = (uint32_t*)(smh + s * STAGE_H + row * ASTR + aq * 16);
            *(uint4*)dst = make_uint4(pk[0], pk[1], pk[2], pk[3]);
            *(uint4*)(dst + 4) = make_uint4(pk[4], pk[5], pk[6], pk[7]);
        }
    };
    auto stageB = [&](int s, int r, int j0) {
        uint32_t sb = sbase + s * STAGE_B + A_H * 2;
        const __half* gb = g_ZH + ((size_t)r * 256 + n0g) * NM + j0;
        #pragma unroll
        for (int h = 0; h < 4; h++) {
            int c = tid + h * 256;
            int n = c >> 3, ch = c & 7;
            uint32_t sa = sb + (uint32_t)(n * (ASTR * 2) + ch * 16);
            CP_ASYNC16(sa, gb + (size_t)n * NM + ch * 8);
        }
        CP_COMMIT();
    };

    uint32_t aAddr[4], bAddr[2];
    #pragma unroll
    for (int mi = 0; mi < 4; mi++) {
        int row = wm * 64 + mi * 16 + (lane & 15);
        aAddr[mi] = sbase + (uint32_t)(row * ASTR + (lane >> 4) * 8) * 2u;
    }
    #pragma unroll
    for (int nj = 0; nj < 2; nj++) {
        int nrow = wn * 32 + nj * 16 + ((lane >> 4) & 1) * 8 + (lane & 7);
        int koff = ((lane >> 3) & 1) * 8;
        bAddr[nj] = sbase + (uint32_t)(A_H * 2) + (uint32_t)(nrow * ASTR + koff) * 2u;
    }

    float dacc[4][4][4];
    #pragma unroll
    for (int mi = 0; mi < 4; mi++)
        #pragma unroll
        for (int ni = 0; ni < 4; ni++)
            #pragma unroll
            for (int q = 0; q < 4; q++) dacc[mi][ni][q] = 0.0f;

    {
        int kg = kbase;
        stageB(0, kg >> 11, kg & 2047);
        buildA(0, kg >> 11, kg & 2047);
    }

    for (int it = 0; it < ITERS; it++) {
        int s = it & 1;
        CP_WAIT0();
        __syncthreads();
        if (it + 1 < ITERS) {
            int kg = kbase + (it + 1) * KT;
            stageB(s ^ 1, kg >> 11, kg & 2047);
            buildA(s ^ 1, kg >> 11, kg & 2047);
        }

        uint32_t soff = (uint32_t)(s * STAGE_B);
        #pragma unroll
        for (int kk = 0; kk < 4; kk++) {
            uint32_t kb = soff + kk * 32;
            uint32_t af[4][4], bf[4][2];
            #pragma unroll
            for (int mi = 0; mi < 4; mi++)
                LDSM_X4(af[mi][0], af[mi][1], af[mi][2], af[mi][3], aAddr[mi] + kb);
            #pragma unroll
            for (int nj = 0; nj < 2; nj++) {
                uint32_t r0, r1, r2, r3;
                LDSM_X4(r0, r1, r2, r3, bAddr[nj] + kb);
                bf[2 * nj][0] = r0;     bf[2 * nj][1] = r1;
                bf[2 * nj + 1][0] = r2; bf[2 * nj + 1][1] = r3;
            }
            #pragma unroll
            for (int mi = 0; mi < 4; mi++)
                #pragma unroll
                for (int ni = 0; ni < 4; ni++)
                    mma_f16(dacc[mi][ni], af[mi], bf[ni][0], bf[ni][1]);
        }
        __syncthreads();
    }

    float* dst = g_part + (size_t)blockIdx.z * NEP * 256;
    #pragma unroll
    for (int mi = 0; mi < 4; mi++) {
        int r0 = i0 + wm * 64 + mi * 16 + gid;
        #pragma unroll
        for (int ni = 0; ni < 4; ni++) {
            int cn = n0g + wn * 32 + ni * 8 + 2 * t4;
            *(float2*)(dst + (size_t)r0 * 256 + cn) = make_float2(dacc[mi][ni][0], dacc[mi][ni][1]);
            *(float2*)(dst + (size_t)(r0 + 8) * 256 + cn) = make_float2(dacc[mi][ni][2], dacc[mi][ni][3]);
        }
    }
}

// ======================= kernel 6: reduce partials + both conv epilogues =====
constexpr int SM_EPI_BYTES = 64 * 132 * 4;
__global__ __launch_bounds__(256, 1) void k_epi(const float* __restrict__ root2,
                                                const float* __restrict__ b2,
                                                float* __restrict__ out) {
    extern __shared__ float sE1[];   // [64][132]
    int i0 = blockIdx.x * 64;
    int tid = threadIdx.x;

    for (int idx = tid; idx < 64 * 32; idx += 256) {
        int e = idx >> 5, q = idx & 31;
        int i = i0 + e;
        float4 v = make_float4(0, 0, 0, 0);
        if (i < NE) {
            float4 s = *(const float4*)(g_ebase + (size_t)i * D + q * 4);
            #pragma unroll
            for (int z = 0; z < KSPLIT; z++) {
                float4 p = *(const float4*)(g_part + ((size_t)z * NEP + i) * 256 + q * 4);
                s.x += p.x; s.y += p.y; s.z += p.z; s.w += p.w;
            }
            v.x = fmaxf(s.x, 0.0f); v.y = fmaxf(s.y, 0.0f);
            v.z = fmaxf(s.z, 0.0f); v.w = fmaxf(s.w, 0.0f);
        }
        *(float4*)(sE1 + e * 132 + q * 4) = v;
    }
    __syncthreads();

    int pe = tid >> 3, cg = tid & 7;
    int eA = pe * 2, eB = pe * 2 + 1;
    int iA = i0 + eA, iB = i0 + eB;
    int c0 = cg * 16;
    float4 oA[4], oB[4];
    #pragma unroll
    for (int q = 0; q < 4; q++) {
        float4 bb = *(const float4*)(b2 + c0 + q * 4);
        float4 gA = make_float4(0, 0, 0, 0), gB = make_float4(0, 0, 0, 0);
        #pragma unroll
        for (int z = 0; z < KSPLIT; z++) {
            if (iA < NE) {
                float4 p = *(const float4*)(g_part + ((size_t)z * NEP + iA) * 256 + 128 + c0 + q * 4);
                gA.x += p.x; gA.y += p.y; gA.z += p.z; gA.w += p.w;
            }
            if (iB < NE) {
                float4 p = *(const float4*)(g_part + ((size_t)z * NEP + iB) * 256 + 128 + c0 + q * 4);
                gB.x += p.x; gB.y += p.y; gB.z += p.z; gB.w += p.w;
            }
        }
        oA[q] = make_float4(bb.x + gA.x, bb.y + gA.y, bb.z + gA.z, bb.w + gA.w);
        oB[q] = make_float4(bb.x + gB.x, bb.y + gB.y, bb.z + gB.z, bb.w + gB.w);
    }
    #pragma unroll 4
    for (int kk = 0; kk < 128; kk++) {
        float evA = sE1[eA * 132 + kk];
        float evB = sE1[eB * 132 + kk];
        const float4* r2 = (const float4*)(root2 + kk * D + c0);
        #pragma unroll
        for (int q = 0; q < 4; q++) {
            float4 r = r2[q];
            oA[q].x += evA * r.x; oA[q].y += evA * r.y; oA[q].z += evA * r.z; oA[q].w += evA * r.w;
            oB[q].x += evB * r.x; oB[q].y += evB * r.y; oB[q].z += evB * r.z; oB[q].w += evB * r.w;
        }
    }
    if (iA < NE) {
        #pragma unroll
        for (int q = 0; q < 4; q++) *(float4*)(out + (size_t)iA * D + c0 + q * 4) = oA[q];
    }
    if (iB < NE) {
        #pragma unroll
        for (int q = 0; q < 4; q++) *(float4*)(out + (size_t)iB * D + c0 + q * 4) = oB[q];
    }
}

// ======================= launch =======================
extern "C" void kernel_launch(void* const* d_in, const int* in_sizes, int n_in,
                              void* d_out, int out_size) {
    const float* xe    = (const float*)d_in[0];
    const float* xm    = (const float*)d_in[1];
    const float* w     = (const float*)d_in[2];
    const float* W1    = (const float*)d_in[3];
    const float* root1 = (const float*)d_in[4];
    const float* b1    = (const float*)d_in[5];
    const float* W2    = (const float*)d_in[6];
    const float* root2 = (const float*)d_in[7];
    const float* b2    = (const float*)d_in[8];
    float* out = (float*)d_out;

    k_lev<<<NE, 256>>>(w);
    k_root1<<<NM / 16 + NE / 16, 128>>>(xm, xe, root1, b1);
    k_Z<<<dim3(NM / 16, 5), 256>>>(xm, W1, W2);

    cudaFuncSetAttribute(k_mma, cudaFuncAttributeMaxDynamicSharedMemorySize, SM_MMA_BYTES);
    k_mma<<<dim3(79, 2, KSPLIT), 256, SM_MMA_BYTES>>>();

    cudaFuncSetAttribute(k_epi, cudaFuncAttributeMaxDynamicSharedMemorySize, SM_EPI_BYTES);
    k_epi<<<(NE + 63) / 64, 256, SM_EPI_BYTES>>>(root2, b2, out);
}

// round 12
// speedup vs baseline: 4.5791x; 1.0506x over previous
#include <cuda_runtime.h>
#include <cuda_fp16.h>
#include <cstdint>

#define NE 10000
#define NM 2048
#define D  128
#define NEP 10112            // 79*128 padded entity count
#define KSPLIT 4

// ======================= device scratch (no allocations allowed) ============
__device__ unsigned char g_lev[(size_t)NE * NM];   // 0 = no edge, 1..5 relation
__device__ __half g_invh[NE * 8];                  // [i][r] 1/cnt (fp16), r=0 -> 0
__device__ float g_m1[NM * D];                     // relu(x_m @ root1 + b1)
__device__ __half g_ZH[(size_t)5 * 256 * NM];      // [r][n][j] K-major fp16 B
__device__ float g_ebase[(size_t)NE * D];          // x_e @ root1 + b1
__device__ float g_part[(size_t)KSPLIT * NEP * 256];  // K-split partials

// ======================= small PTX helpers ============
#define CP_ASYNC16(s, g) asm volatile("cp.async.cg.shared.global [%0], [%1], 16;" :: "r"(s), "l"(g))
#define CP_COMMIT()      asm volatile("cp.async.commit_group;" ::: "memory")
#define CP_WAIT0()       asm volatile("cp.async.wait_group 0;" ::: "memory")
#define LDSM_X4(r0, r1, r2, r3, a)                                                   \
    asm volatile("ldmatrix.sync.aligned.m8n8.x4.shared.b16 {%0,%1,%2,%3}, [%4];"     \
                 : "=r"(r0), "=r"(r1), "=r"(r2), "=r"(r3) : "r"(a))

__device__ __forceinline__ uint32_t smem_u32(const void* p) {
    uint32_t a;
    asm("{ .reg .u64 t; cvta.to.shared.u64 t, %1; cvt.u32.u64 %0, t; }" : "=r"(a) : "l"(p));
    return a;
}

__device__ __forceinline__ void mma_f16(float* d, const uint32_t* a, uint32_t b0, uint32_t b1) {
    asm volatile(
        "mma.sync.aligned.m16n8k16.row.col.f32.f16.f16.f32 "
        "{%0,%1,%2,%3}, {%4,%5,%6,%7}, {%8,%9}, {%0,%1,%2,%3};"
        : "+f"(d[0]), "+f"(d[1]), "+f"(d[2]), "+f"(d[3])
        : "r"(a[0]), "r"(a[1]), "r"(a[2]), "r"(a[3]), "r"(b0), "r"(b1));
}

// ======================= kernel 1: levels + inverse counts (fp16) ============
__global__ void k_lev(const float* __restrict__ w) {
    int i = blockIdx.x;
    __shared__ int scnt[5];
    if (threadIdx.x < 5) scnt[threadIdx.x] = 0;
    __syncthreads();
    int cnt[5] = {0, 0, 0, 0, 0};
    const float* wr = w + (size_t)i * NM;
    unsigned char* lr = g_lev + (size_t)i * NM;
    #pragma unroll
    for (int s = 0; s < 8; s++) {
        int j = threadIdx.x + s * 256;
        float v = wr[j];
        int lv = (int)ceilf(v * 6.0f) - 1;
        int o = (lv >= 1 && lv <= 5) ? lv : 0;
        lr[j] = (unsigned char)o;
        if (o) cnt[o - 1]++;
    }
    #pragma unroll
    for (int r = 0; r < 5; r++) {
        int v = cnt[r];
        #pragma unroll
        for (int off = 16; off; off >>= 1) v += __shfl_down_sync(0xffffffffu, v, off);
        if ((threadIdx.x & 31) == 0) atomicAdd(&scnt[r], v);
    }
    __syncthreads();
    if (threadIdx.x < 8) {
        float iv = 0.0f;
        if (threadIdx.x >= 1 && threadIdx.x <= 5) {
            int c = scnt[threadIdx.x - 1];
            iv = (c > 0) ? 1.0f / (float)c : 0.0f;
        }
        g_invh[i * 8 + threadIdx.x] = __float2half(iv);
    }
}

// ======================= kernel 2: root1 transform (moles + entities) ========
__global__ void k_root1(const float* __restrict__ xm, const float* __restrict__ xe,
                        const float* __restrict__ root1, const float* __restrict__ b1) {
    __shared__ float xs[128][20];
    int bi = blockIdx.x;
    bool mole = bi < (NM / 16);
    int r0 = mole ? bi * 16 : (bi - NM / 16) * 16;
    const float* src = (mole ? xm : xe) + (size_t)r0 * D;
    int c = threadIdx.x;
    for (int t = c; t < 16 * 128; t += 128) {
        int e = t >> 7, k = t & 127;
        xs[k][e] = src[e * D + k];
    }
    __syncthreads();
    float a[16];
    #pragma unroll
    for (int e = 0; e < 16; e++) a[e] = 0.0f;
    #pragma unroll 2
    for (int k = 0; k < 128; k++) {
        float wv = root1[k * D + c];
        float4 x0 = *(const float4*)&xs[k][0];
        float4 x1 = *(const float4*)&xs[k][4];
        float4 x2 = *(const float4*)&xs[k][8];
        float4 x3 = *(const float4*)&xs[k][12];
        a[0] += x0.x * wv; a[1] += x0.y * wv; a[2] += x0.z * wv; a[3] += x0.w * wv;
        a[4] += x1.x * wv; a[5] += x1.y * wv; a[6] += x1.z * wv; a[7] += x1.w * wv;
        a[8] += x2.x * wv; a[9] += x2.y * wv; a[10] += x2.z * wv; a[11] += x2.w * wv;
        a[12] += x3.x * wv; a[13] += x3.y * wv; a[14] += x3.z * wv; a[15] += x3.w * wv;
    }
    float bb = b1[c];
    if (mole) {
        #pragma unroll
        for (int e = 0; e < 16; e++) g_m1[(size_t)(r0 + e) * D + c] = fmaxf(a[e] + bb, 0.0f);
    } else {
        #pragma unroll
        for (int e = 0; e < 16; e++) g_ebase[(size_t)(r0 + e) * D + c] = a[e] + bb;
    }
}

// ======================= kernel 4: ZH[r][n][j] = fp16 K-major ================
__global__ void k_Z(const float* __restrict__ xm, const float* __restrict__ W1,
                    const float* __restrict__ W2) {
    __shared__ float xs[128][20], ms[128][20];
    int ri = blockIdx.y;
    int j0 = blockIdx.x * 16;
    for (int t = threadIdx.x; t < 16 * 128; t += 256) {
        int e = t >> 7, k = t & 127;
        xs[k][e] = xm[(size_t)(j0 + e) * D + k];
        ms[k][e] = g_m1[(size_t)(j0 + e) * D + k];
    }
    __syncthreads();
    int c = threadIdx.x;
    int cc = c & 127;
    const float* W = ((c < 128) ? W1 : W2) + (size_t)(ri + 1) * D * D;
    const float(*S)[20] = (c < 128) ? xs : ms;
    float a[16];
    #pragma unroll
    for (int e = 0; e < 16; e++) a[e] = 0.0f;
    #pragma unroll 2
    for (int k = 0; k < 128; k++) {
        float wv = W[k * D + cc];
        float4 x0 = *(const float4*)&S[k][0];
        float4 x1 = *(const float4*)&S[k][4];
        float4 x2 = *(const float4*)&S[k][8];
        float4 x3 = *(const float4*)&S[k][12];
        a[0] += x0.x * wv; a[1] += x0.y * wv; a[2] += x0.z * wv; a[3] += x0.w * wv;
        a[4] += x1.x * wv; a[5] += x1.y * wv; a[6] += x1.z * wv; a[7] += x1.w * wv;
        a[8] += x2.x * wv; a[9] += x2.y * wv; a[10] += x2.z * wv; a[11] += x2.w * wv;
        a[12] += x3.x * wv; a[13] += x3.y * wv; a[14] += x3.z * wv; a[15] += x3.w * wv;
    }
    __half2* dst = (__half2*)(g_ZH + ((size_t)ri * 256 + c) * NM + j0);
    #pragma unroll
    for (int e = 0; e < 8; e++) dst[e] = __floats2half2_rn(a[2 * e], a[2 * e + 1]);
}

// ======================= kernel 5: fp16 mask-GEMM, M64xN128 CTA tile =========
// grid (158, 2, 4): x = M tile (64), y = N half (128), z = K quarter (2560).
// 256 threads, 8 warps: wm = wid&1 (2 x 32 rows), wn = wid>>1 (4 x 32 cols).
// 3 CTAs per SM (regs <= 85, smem 54KB/CTA).
constexpr int KT = 64;
constexpr int KQ = 10240 / KSPLIT;             // 2560
constexpr int ITERS = KQ / KT;                 // 40
constexpr int ASTR = 72;
constexpr int A_H = 64 * ASTR;                 // 4608 halfs
constexpr int B_H = 128 * ASTR;                // 9216 halfs
constexpr int STAGE_H = A_H + B_H;             // 13824 halfs
constexpr int STAGE_B = STAGE_H * 2;           // 27648 bytes
constexpr int SM_MMA_BYTES = 2 * STAGE_B;      // 55296 bytes

__global__ __launch_bounds__(256, 3) void k_mma() {
    extern __shared__ __half smh[];
    uint32_t sbase = smem_u32(smh);

    int tid = threadIdx.x;
    int wid = tid >> 5, lane = tid & 31;
    int gid = lane >> 2, t4 = lane & 3;
    int wm = wid & 1, wn = wid >> 1;

    int i0 = blockIdx.x * 64;
    int n0g = blockIdx.y * 128;
    int kbase = blockIdx.z * KQ;

    // A-build role: row = tid>>2 (0..63), 16-lev-byte chunk aq = tid&3
    int arow = tid >> 2, aq = tid & 3;
    int gr = min(i0 + arow, NE - 1);
    const unsigned char* levrow = g_lev + (size_t)gr * NM;
    const __half* invrow = g_invh + (size_t)gr * 8;

    auto buildA = [&](int s, int r, int j0) {
        unsigned char rv = (unsigned char)(r + 1);
        uint4 u = *(const uint4*)(levrow + j0 + aq * 16);
        unsigned char bts[16];
        *(uint4*)bts = u;
        __half ivh = invrow[r + 1];
        __half z = __ushort_as_half((unsigned short)0);
        uint32_t pk[8];
        #pragma unroll
        for (int q = 0; q < 8; q++) {
            __half2 h2;
            h2.x = (bts[2 * q] == rv) ? ivh : z;
            h2.y = (bts[2 * q + 1] == rv) ? ivh : z;
            pk[q] = *(uint32_t*)&h2;
        }
        uint32_t* dst = (uint32_t*)(smh + s * STAGE_H + arow * ASTR + aq * 16);
        *(uint4*)dst = make_uint4(pk[0], pk[1], pk[2], pk[3]);
        *(uint4*)(dst + 4) = make_uint4(pk[4], pk[5], pk[6], pk[7]);
    };
    auto stageB = [&](int s, int r, int j0) {
        uint32_t sb = sbase + s * STAGE_B + A_H * 2;
        const __half* gb = g_ZH + ((size_t)r * 256 + n0g) * NM + j0;
        #pragma unroll
        for (int h = 0; h < 4; h++) {
            int c = tid + h * 256;
            int n = c >> 3, ch = c & 7;
            uint32_t sa = sb + (uint32_t)(n * (ASTR * 2) + ch * 16);
            CP_ASYNC16(sa, gb + (size_t)n * NM + ch * 8);
        }
        CP_COMMIT();
    };

    uint32_t aAddr[2], bAddr[2];
    #pragma unroll
    for (int mi = 0; mi < 2; mi++) {
        int row = wm * 32 + mi * 16 + (lane & 15);
        aAddr[mi] = sbase + (uint32_t)(row * ASTR + (lane >> 4) * 8) * 2u;
    }
    #pragma unroll
    for (int nj = 0; nj < 2; nj++) {
        int nrow = wn * 32 + nj * 16 + ((lane >> 4) & 1) * 8 + (lane & 7);
        int koff = ((lane >> 3) & 1) * 8;
        bAddr[nj] = sbase + (uint32_t)(A_H * 2) + (uint32_t)(nrow * ASTR + koff) * 2u;
    }

    float dacc[2][4][4];
    #pragma unroll
    for (int mi = 0; mi < 2; mi++)
        #pragma unroll
        for (int ni = 0; ni < 4; ni++)
            #pragma unroll
            for (int q = 0; q < 4; q++) dacc[mi][ni][q] = 0.0f;

    {
        int kg = kbase;
        stageB(0, kg >> 11, kg & 2047);
        buildA(0, kg >> 11, kg & 2047);
    }

    for (int it = 0; it < ITERS; it++) {
        int s = it & 1;
        CP_WAIT0();
        __syncthreads();
        if (it + 1 < ITERS) {
            int kg = kbase + (it + 1) * KT;
            stageB(s ^ 1, kg >> 11, kg & 2047);
            buildA(s ^ 1, kg >> 11, kg & 2047);
        }

        uint32_t soff = (uint32_t)(s * STAGE_B);
        #pragma unroll
        for (int kk = 0; kk < 4; kk++) {
            uint32_t kb = soff + kk * 32;
            uint32_t af[2][4], bf[4][2];
            #pragma unroll
            for (int mi = 0; mi < 2; mi++)
                LDSM_X4(af[mi][0], af[mi][1], af[mi][2], af[mi][3], aAddr[mi] + kb);
            #pragma unroll
            for (int nj = 0; nj < 2; nj++) {
                uint32_t r0, r1, r2, r3;
                LDSM_X4(r0, r1, r2, r3, bAddr[nj] + kb);
                bf[2 * nj][0] = r0;     bf[2 * nj][1] = r1;
                bf[2 * nj + 1][0] = r2; bf[2 * nj + 1][1] = r3;
            }
            #pragma unroll
            for (int mi = 0; mi < 2; mi++)
                #pragma unroll
                for (int ni = 0; ni < 4; ni++)
                    mma_f16(dacc[mi][ni], af[mi], bf[ni][0], bf[ni][1]);
        }
        __syncthreads();
    }

    float* dst = g_part + (size_t)blockIdx.z * NEP * 256;
    #pragma unroll
    for (int mi = 0; mi < 2; mi++) {
        int r0 = i0 + wm * 32 + mi * 16 + gid;
        #pragma unroll
        for (int ni = 0; ni < 4; ni++) {
            int cn = n0g + wn * 32 + ni * 8 + 2 * t4;
            *(float2*)(dst + (size_t)r0 * 256 + cn) = make_float2(dacc[mi][ni][0], dacc[mi][ni][1]);
            *(float2*)(dst + (size_t)(r0 + 8) * 256 + cn) = make_float2(dacc[mi][ni][2], dacc[mi][ni][3]);
        }
    }
}

// ======================= kernel 6: reduce partials + both conv epilogues =====
constexpr int SM_EPI_BYTES = 64 * 132 * 4;
__global__ __launch_bounds__(256, 1) void k_epi(const float* __restrict__ root2,
                                                const float* __restrict__ b2,
                                                float* __restrict__ out) {
    extern __shared__ float sE1[];   // [64][132]
    int i0 = blockIdx.x * 64;
    int tid = threadIdx.x;

    for (int idx = tid; idx < 64 * 32; idx += 256) {
        int e = idx >> 5, q = idx & 31;
        int i = i0 + e;
        float4 v = make_float4(0, 0, 0, 0);
        if (i < NE) {
            float4 s = *(const float4*)(g_ebase + (size_t)i * D + q * 4);
            #pragma unroll
            for (int z = 0; z < KSPLIT; z++) {
                float4 p = *(const float4*)(g_part + ((size_t)z * NEP + i) * 256 + q * 4);
                s.x += p.x; s.y += p.y; s.z += p.z; s.w += p.w;
            }
            v.x = fmaxf(s.x, 0.0f); v.y = fmaxf(s.y, 0.0f);
            v.z = fmaxf(s.z, 0.0f); v.w = fmaxf(s.w, 0.0f);
        }
        *(float4*)(sE1 + e * 132 + q * 4) = v;
    }
    __syncthreads();

    int pe = tid >> 3, cg = tid & 7;
    int eA = pe * 2, eB = pe * 2 + 1;
    int iA = i0 + eA, iB = i0 + eB;
    int c0 = cg * 16;
    float4 oA[4], oB[4];
    #pragma unroll
    for (int q = 0; q < 4; q++) {
        float4 bb = *(const float4*)(b2 + c0 + q * 4);
        float4 gA = make_float4(0, 0, 0, 0), gB = make_float4(0, 0, 0, 0);
        #pragma unroll
        for (int z = 0; z < KSPLIT; z++) {
            if (iA < NE) {
                float4 p = *(const float4*)(g_part + ((size_t)z * NEP + iA) * 256 + 128 + c0 + q * 4);
                gA.x += p.x; gA.y += p.y; gA.z += p.z; gA.w += p.w;
            }
            if (iB < NE) {
                float4 p = *(const float4*)(g_part + ((size_t)z * NEP + iB) * 256 + 128 + c0 + q * 4);
                gB.x += p.x; gB.y += p.y; gB.z += p.z; gB.w += p.w;
            }
        }
        oA[q] = make_float4(bb.x + gA.x, bb.y + gA.y, bb.z + gA.z, bb.w + gA.w);
        oB[q] = make_float4(bb.x + gB.x, bb.y + gB.y, bb.z + gB.z, bb.w + gB.w);
    }
    #pragma unroll 4
    for (int kk = 0; kk < 128; kk++) {
        float evA = sE1[eA * 132 + kk];
        float evB = sE1[eB * 132 + kk];
        const float4* r2 = (const float4*)(root2 + kk * D + c0);
        #pragma unroll
        for (int q = 0; q < 4; q++) {
            float4 r = r2[q];
            oA[q].x += evA * r.x; oA[q].y += evA * r.y; oA[q].z += evA * r.z; oA[q].w += evA * r.w;
            oB[q].x += evB * r.x; oB[q].y += evB * r.y; oB[q].z += evB * r.z; oB[q].w += evB * r.w;
        }
    }
    if (iA < NE) {
        #pragma unroll
        for (int q = 0; q < 4; q++) *(float4*)(out + (size_t)iA * D + c0 + q * 4) = oA[q];
    }
    if (iB < NE) {
        #pragma unroll
        for (int q = 0; q < 4; q++) *(float4*)(out + (size_t)iB * D + c0 + q * 4) = oB[q];
    }
}

// ======================= launch =======================
extern "C" void kernel_launch(void* const* d_in, const int* in_sizes, int n_in,
                              void* d_out, int out_size) {
    const float* xe    = (const float*)d_in[0];
    const float* xm    = (const float*)d_in[1];
    const float* w     = (const float*)d_in[2];
    const float* W1    = (const float*)d_in[3];
    const float* root1 = (const float*)d_in[4];
    const float* b1    = (const float*)d_in[5];
    const float* W2    = (const float*)d_in[6];
    const float* root2 = (const float*)d_in[7];
    const float* b2    = (const float*)d_in[8];
    float* out = (float*)d_out;

    k_lev<<<NE, 256>>>(w);
    k_root1<<<NM / 16 + NE / 16, 128>>>(xm, xe, root1, b1);
    k_Z<<<dim3(NM / 16, 5), 256>>>(xm, W1, W2);

    cudaFuncSetAttribute(k_mma, cudaFuncAttributeMaxDynamicSharedMemorySize, SM_MMA_BYTES);
    k_mma<<<dim3(158, 2, KSPLIT), 256, SM_MMA_BYTES>>>();

    cudaFuncSetAttribute(k_epi, cudaFuncAttributeMaxDynamicSharedMemorySize, SM_EPI_BYTES);
    k_epi<<<(NE + 63) / 64, 256, SM_EPI_BYTES>>>(root2, b2, out);
}